// round 1
// baseline (speedup 1.0000x reference)
#include <cuda_runtime.h>
#include <math.h>

#define BB 8
#define TT 2048
#define CC 1024
#define HH 64
#define BT (BB*TT)

// ---------------- scratch (__device__ globals; no allocs allowed) ----------
__device__ float g_q[BT*HH];
__device__ float g_k[BT*HH];
__device__ float g_v[BT*HH];

// flash-decoding partials: per (b, triangular chunk) x 128 query rows
// chunks per batch: sum_{qt=0..15} (qt+1) = 136
#define NCHUNK 136
__device__ float g_pacc[(size_t)BB*NCHUNK*HH*128];  // [chunk][h][row]
__device__ float g_pm_[(size_t)BB*NCHUNK*128];
__device__ float g_pl_[(size_t)BB*NCHUNK*128];

// ---------------- projection: out = x @ W for W in {Wq,Wk,Wv} -------------
// block: 256 threads, tile 128 rows x 64 cols, K-chunk 32
#define PTM 128
#define PTK 32

__global__ __launch_bounds__(256) void proj_kernel(
    const float* __restrict__ x,
    const float* __restrict__ Wq,
    const float* __restrict__ Wk,
    const float* __restrict__ Wv)
{
    const int rt = blockIdx.x;            // row tile 0..127
    const int which = blockIdx.y;         // 0=q 1=k 2=v
    const float* __restrict__ W = (which == 0) ? Wq : (which == 1) ? Wk : Wv;
    float* __restrict__ out = (which == 0) ? g_q : (which == 1) ? g_k : g_v;

    __shared__ float XS[PTM][PTK + 4];    // pad 4 floats: bank spread + 16B align
    __shared__ float WS[PTK][HH];

    const int tid = threadIdx.x;
    const int tx = tid & 15;              // col group: cols 4*tx .. 4*tx+3
    const int ty = tid >> 4;              // row group: rows 8*ty .. 8*ty+7
    const int row0 = rt * PTM;

    float acc[8][4];
    #pragma unroll
    for (int i = 0; i < 8; i++)
        #pragma unroll
        for (int j = 0; j < 4; j++) acc[i][j] = 0.f;

    for (int kc = 0; kc < CC; kc += PTK) {
        // load XS: 128x32 floats = 1024 float4, 4 per thread
        #pragma unroll
        for (int i = tid; i < 1024; i += 256) {
            int r = i >> 3, c4 = (i & 7) << 2;
            *(float4*)&XS[r][c4] =
                *(const float4*)&x[(size_t)(row0 + r) * CC + kc + c4];
        }
        // load WS: 32x64 floats = 512 float4, 2 per thread
        #pragma unroll
        for (int i = tid; i < 512; i += 256) {
            int r = i >> 4, c4 = (i & 15) << 2;
            *(float4*)&WS[r][c4] =
                *(const float4*)&W[(size_t)(kc + r) * HH + c4];
        }
        __syncthreads();

        #pragma unroll
        for (int k = 0; k < PTK; k++) {
            float4 bv = *(float4*)&WS[k][tx << 2];
            #pragma unroll
            for (int i = 0; i < 8; i++) {
                float a = XS[ty * 8 + i][k];
                acc[i][0] = fmaf(a, bv.x, acc[i][0]);
                acc[i][1] = fmaf(a, bv.y, acc[i][1]);
                acc[i][2] = fmaf(a, bv.z, acc[i][2]);
                acc[i][3] = fmaf(a, bv.w, acc[i][3]);
            }
        }
        __syncthreads();
    }

    #pragma unroll
    for (int i = 0; i < 8; i++) {
        float4 o = make_float4(acc[i][0], acc[i][1], acc[i][2], acc[i][3]);
        *(float4*)&out[(size_t)(row0 + ty * 8 + i) * HH + (tx << 2)] = o;
    }
}

// ---------------- attention pass 1: partial flash over a 128-key chunk ----
// grid: B*136 uniform blocks; block: 128 threads (1 thread = 1 query row)
__global__ __launch_bounds__(128) void attn_partial(const int* __restrict__ pad_mask)
{
    const int bx = blockIdx.x;
    const int b = bx / NCHUNK;
    const int r = bx % NCHUNK;
    int qt = 0;
    while ((qt + 1) * (qt + 2) / 2 <= r) qt++;     // triangular decode
    const int kc = r - qt * (qt + 1) / 2;

    const int tid = threadIdx.x;
    const int qrow = qt * 128 + tid;               // global query index
    const int k0 = kc * 128;                       // key chunk start

    // q row in registers, pre-scaled by 1/sqrt(C) = 1/32
    float q[HH];
    {
        const float* qp = g_q + ((size_t)(b * TT + qrow)) * HH;
        #pragma unroll
        for (int i = 0; i < 16; i++) {
            float4 t4 = *(const float4*)(qp + i * 4);
            q[i * 4 + 0] = t4.x * 0.03125f;
            q[i * 4 + 1] = t4.y * 0.03125f;
            q[i * 4 + 2] = t4.z * 0.03125f;
            q[i * 4 + 3] = t4.w * 0.03125f;
        }
    }

    float m = -1e30f, l = 0.f;
    float acc[HH];
    #pragma unroll
    for (int h = 0; h < HH; h++) acc[h] = 0.f;

    __shared__ float KS[64][64];
    __shared__ float VS[64][64];
    __shared__ int   PM[64];

    for (int t2 = 0; t2 < 2; t2++) {
        const int kbase = k0 + t2 * 64;
        // cooperative load: 64x64 floats each = 1024 float4, 8/thread
        #pragma unroll
        for (int i = tid; i < 1024; i += 128) {
            int row = i >> 4, c4 = (i & 15) << 2;
            size_t g = ((size_t)(b * TT + kbase + row)) * HH + c4;
            *(float4*)&KS[row][c4] = *(const float4*)&g_k[g];
            *(float4*)&VS[row][c4] = *(const float4*)&g_v[g];
        }
        if (tid < 64) PM[tid] = pad_mask[b * TT + kbase + tid];
        __syncthreads();

        for (int jc = 0; jc < 4; jc++) {
            float s[16];
            #pragma unroll
            for (int j = 0; j < 16; j++) {
                const int jj = jc * 16 + j;
                float d = 0.f;
                #pragma unroll
                for (int k4 = 0; k4 < 16; k4++) {
                    float4 kv = *(float4*)&KS[jj][k4 << 2];  // warp-broadcast
                    d = fmaf(q[k4 * 4 + 0], kv.x, d);
                    d = fmaf(q[k4 * 4 + 1], kv.y, d);
                    d = fmaf(q[k4 * 4 + 2], kv.z, d);
                    d = fmaf(q[k4 * 4 + 3], kv.w, d);
                }
                const int jg = kbase + jj;
                s[j] = (jg <= qrow && PM[jj] != 0) ? d : -1e30f;
            }
            float mc = s[0];
            #pragma unroll
            for (int j = 1; j < 16; j++) mc = fmaxf(mc, s[j]);
            float mnew = fmaxf(m, mc);
            if (mnew <= -1e29f) continue;           // chunk fully masked

            float alpha = __expf(m - mnew);
            m = mnew;
            l *= alpha;
            #pragma unroll
            for (int h = 0; h < HH; h++) acc[h] *= alpha;

            #pragma unroll
            for (int j = 0; j < 16; j++) {
                const int jj = jc * 16 + j;
                float p = __expf(s[j] - mnew);
                l += p;
                #pragma unroll
                for (int h4 = 0; h4 < 16; h4++) {
                    float4 vv = *(float4*)&VS[jj][h4 << 2];  // warp-broadcast
                    acc[h4 * 4 + 0] = fmaf(p, vv.x, acc[h4 * 4 + 0]);
                    acc[h4 * 4 + 1] = fmaf(p, vv.y, acc[h4 * 4 + 1]);
                    acc[h4 * 4 + 2] = fmaf(p, vv.z, acc[h4 * 4 + 2]);
                    acc[h4 * 4 + 3] = fmaf(p, vv.w, acc[h4 * 4 + 3]);
                }
            }
        }
        __syncthreads();
    }

    // store partials: acc transposed [chunk][h][row] for coalesced combine
    const size_t ci = (size_t)bx;
    g_pm_[ci * 128 + tid] = m;
    g_pl_[ci * 128 + tid] = l;
    float* pa = g_pacc + ci * (HH * 128);
    #pragma unroll
    for (int h = 0; h < HH; h++) pa[h * 128 + tid] = acc[h];
}

// ---------------- attention pass 2: combine partials -----------------------
// grid: (16 qtiles, 8 batches), 128 threads (1 thread = 1 query row)
__global__ __launch_bounds__(128) void attn_combine(float* __restrict__ out)
{
    const int qt = blockIdx.x;
    const int b = blockIdx.y;
    const int row = threadIdx.x;
    const int np = qt + 1;
    const size_t base = (size_t)b * NCHUNK + qt * (qt + 1) / 2;

    float mstar = -1e30f;
    for (int p = 0; p < np; p++)
        mstar = fmaxf(mstar, g_pm_[(base + p) * 128 + row]);

    float L = 0.f;
    float o[HH];
    #pragma unroll
    for (int h = 0; h < HH; h++) o[h] = 0.f;

    for (int p = 0; p < np; p++) {
        const size_t ci = base + p;
        float w = __expf(g_pm_[ci * 128 + row] - mstar);
        L += g_pl_[ci * 128 + row] * w;
        const float* pa = g_pacc + ci * (HH * 128);
        #pragma unroll
        for (int h = 0; h < HH; h++) o[h] = fmaf(w, pa[h * 128 + row], o[h]);
    }

    const float inv = 1.f / L;
    float* op = out + ((size_t)(b * TT + qt * 128 + row)) * HH;
    #pragma unroll
    for (int h4 = 0; h4 < 16; h4++) {
        float4 v = make_float4(o[h4 * 4 + 0] * inv, o[h4 * 4 + 1] * inv,
                               o[h4 * 4 + 2] * inv, o[h4 * 4 + 3] * inv);
        *(float4*)&op[h4 << 2] = v;
    }
}

// ---------------- launcher -------------------------------------------------
extern "C" void kernel_launch(void* const* d_in, const int* in_sizes, int n_in,
                              void* d_out, int out_size)
{
    const float* x        = (const float*)d_in[0];
    const int*   pad_mask = (const int*)d_in[1];
    const float* Wq       = (const float*)d_in[2];
    const float* Wk       = (const float*)d_in[3];
    const float* Wv       = (const float*)d_in[4];
    float* out = (float*)d_out;

    proj_kernel<<<dim3(BT / PTM, 3), 256>>>(x, Wq, Wk, Wv);
    attn_partial<<<BB * NCHUNK, 128>>>(pad_mask);
    attn_combine<<<dim3(16, BB), 128>>>(out);
}

// round 9
// speedup vs baseline: 1.3295x; 1.3295x over previous
#include <cuda_runtime.h>
#include <cuda_bf16.h>
#include <mma.h>
#include <cstdint>
#include <math.h>

using namespace nvcuda;

#define BB 8
#define TT 2048
#define CC 1024
#define HH 64
#define BT (BB*TT)

// ---------------- scratch (__device__ globals; no allocs allowed) ----------
__device__ float g_q[BT*HH];
__device__ float g_k[BT*HH];
__device__ float g_v[BT*HH];
// W split into bf16 hi/lo, ORIGINAL [k][n] layout per matrix: [mi][k=0..1023][n=0..63]
__device__ __nv_bfloat16 g_wh[3*CC*HH];
__device__ __nv_bfloat16 g_wl[3*CC*HH];

// flash-decoding partials
#define NCHUNK 136
__device__ float g_pacc[(size_t)BB*NCHUNK*HH*128];
__device__ float g_pm_[(size_t)BB*NCHUNK*128];
__device__ float g_pl_[(size_t)BB*NCHUNK*128];

__device__ __forceinline__ void cp_async16(uint32_t dst, const void* src) {
    asm volatile("cp.async.cg.shared.global [%0], [%1], 16;"
                 :: "r"(dst), "l"(src) : "memory");
}
__device__ __forceinline__ uint32_t smem_u32(const void* p) {
    uint32_t a;
    asm("{ .reg .u64 t; cvta.to.shared.u64 t, %1; cvt.u32.u64 %0, t; }"
        : "=r"(a) : "l"(p));
    return a;
}

// ==================== W split pre-kernel (no transpose) ====================
__global__ __launch_bounds__(256) void wt_convert(
    const float* __restrict__ Wq, const float* __restrict__ Wk,
    const float* __restrict__ Wv)
{
    int idx = blockIdx.x * 256 + threadIdx.x;      // 3*1024*64 = 196608
    int mi = idx >> 16;
    int rem = idx & 65535;                         // k*64 + n
    const float* W = (mi == 0) ? Wq : (mi == 1) ? Wk : Wv;
    float w = W[rem];
    __nv_bfloat16 h = __float2bfloat16_rn(w);
    float r = w - __bfloat162float(h);
    g_wh[(size_t)mi * 65536 + rem] = h;
    g_wl[(size_t)mi * 65536 + rem] = __float2bfloat16_rn(r);
}

// ==================== wmma projection GEMM ====================
// CTA: out tile [128 rows x 192 cols (q|k|v)] = X[128,1024] @ W[1024,192]
// bf16 split: Xh*Wh + Xh*Wl + Xl*Wh, fp32 accumulate.
// LDMs chosen so every wmma fragment pointer is 32B-aligned:
//   A_LDM=48 elems (96B rows), B_LDM=208 elems (416B rows).
#define A_LDM 48
#define B_LDM 208
#define A_BYTES (128*A_LDM*2)          // 12288
#define B_BYTES (32*B_LDM*2)           // 13312
#define OFF_AL  A_BYTES                // 12288
#define OFF_BH  (2*A_BYTES)            // 24576
#define OFF_BL  (2*A_BYTES + B_BYTES)  // 37888
#define STAGE_BYTES (2*A_BYTES + 2*B_BYTES)  // 51200
#define DYN_BYTES (2*STAGE_BYTES)      // 102400

__global__ __launch_bounds__(256) void proj_wmma(const float* __restrict__ x)
{
    extern __shared__ char dyn[];
    char* sm = dyn;
    const uint32_t smb = smem_u32(dyn);
    const int tid = threadIdx.x;
    const int row0 = blockIdx.x * 128;

    const int warp = tid >> 5;
    const int wm = warp >> 1;          // 0..3 : rows wm*32
    const int wn = warp & 1;           // 0..1 : cols wn*96

    // A-load mapping: each thread owns one row-half (16 fp32)
    const int a_row = tid >> 1;
    const int a_c0 = (tid & 1) * 16;

    wmma::fragment<wmma::accumulator, 16, 16, 16, float> acc[2][6];
    #pragma unroll
    for (int m = 0; m < 2; m++)
        #pragma unroll
        for (int n = 0; n < 6; n++)
            wmma::fill_fragment(acc[m][n], 0.0f);

    auto load_B = [&](int stage, int kc) {
        // 2 precisions x 32 rows x 24 col-chunks(8 bf16) = 1536 chunks, 6/thread
        const uint32_t bbase = smb + stage * STAGE_BYTES;
        #pragma unroll
        for (int t = 0; t < 6; t++) {
            int j = tid + t * 256;
            int prec = (j >= 768) ? 1 : 0;         // 0=hi, 1=lo
            int r = j - prec * 768;                // FIXED (was j & 767)
            int row = r / 24;                      // k within chunk, 0..31
            int c = (r % 24) * 8;                  // col 0..191 step 8
            int mi = c >> 6, n = c & 63;
            const __nv_bfloat16* src = (prec ? g_wl : g_wh)
                + (size_t)mi * 65536 + (size_t)(kc + row) * HH + n;
            uint32_t dst = bbase + (prec ? OFF_BL : OFF_BH)
                         + (uint32_t)(row * B_LDM + c) * 2;
            cp_async16(dst, src);
        }
        asm volatile("cp.async.commit_group;" ::: "memory");
    };

    auto load_A_regs = [&](int kc, float4* va) {
        const float* px = x + (size_t)(row0 + a_row) * CC + kc + a_c0;
        #pragma unroll
        for (int i = 0; i < 4; i++) va[i] = *(const float4*)(px + i * 4);
    };

    auto store_A = [&](int stage, const float4* va) {
        float v[16];
        #pragma unroll
        for (int i = 0; i < 4; i++) {
            v[i*4+0] = va[i].x; v[i*4+1] = va[i].y;
            v[i*4+2] = va[i].z; v[i*4+3] = va[i].w;
        }
        __align__(16) __nv_bfloat16 h[16];
        __align__(16) __nv_bfloat16 l[16];
        #pragma unroll
        for (int e = 0; e < 16; e++) {
            h[e] = __float2bfloat16_rn(v[e]);
            l[e] = __float2bfloat16_rn(v[e] - __bfloat162float(h[e]));
        }
        char* ab = sm + stage * STAGE_BYTES + (size_t)(a_row * A_LDM + a_c0) * 2;
        *(uint4*)(ab)               = *(uint4*)(h);
        *(uint4*)(ab + 16)          = *(uint4*)(h + 8);
        *(uint4*)(ab + OFF_AL)      = *(uint4*)(l);
        *(uint4*)(ab + OFF_AL + 16) = *(uint4*)(l + 8);
    };

    auto compute = [&](int stage) {
        const __nv_bfloat16* Ah = (const __nv_bfloat16*)(sm + stage * STAGE_BYTES);
        const __nv_bfloat16* Al = (const __nv_bfloat16*)(sm + stage * STAGE_BYTES + OFF_AL);
        const __nv_bfloat16* Bh = (const __nv_bfloat16*)(sm + stage * STAGE_BYTES + OFF_BH);
        const __nv_bfloat16* Bl = (const __nv_bfloat16*)(sm + stage * STAGE_BYTES + OFF_BL);
        #pragma unroll
        for (int ks = 0; ks < 2; ks++) {
            wmma::fragment<wmma::matrix_a, 16, 16, 16, __nv_bfloat16, wmma::row_major> ah[2], al[2];
            #pragma unroll
            for (int m = 0; m < 2; m++) {
                const int r = wm * 32 + m * 16;
                wmma::load_matrix_sync(ah[m], Ah + r * A_LDM + ks * 16, A_LDM);
                wmma::load_matrix_sync(al[m], Al + r * A_LDM + ks * 16, A_LDM);
            }
            #pragma unroll
            for (int n = 0; n < 6; n++) {
                const int c = wn * 96 + n * 16;
                wmma::fragment<wmma::matrix_b, 16, 16, 16, __nv_bfloat16, wmma::row_major> bh, bl;
                wmma::load_matrix_sync(bh, Bh + ks * 16 * B_LDM + c, B_LDM);
                wmma::load_matrix_sync(bl, Bl + ks * 16 * B_LDM + c, B_LDM);
                #pragma unroll
                for (int m = 0; m < 2; m++) {
                    wmma::mma_sync(acc[m][n], ah[m], bh, acc[m][n]);
                    wmma::mma_sync(acc[m][n], ah[m], bl, acc[m][n]);
                    wmma::mma_sync(acc[m][n], al[m], bh, acc[m][n]);
                }
            }
        }
    };

    // ---- pipelined main loop over 32 K-chunks of 32 ----
    {
        float4 va[4];
        load_B(0, 0);
        load_A_regs(0, va);
        store_A(0, va);
        asm volatile("cp.async.wait_group 0;" ::: "memory");
        __syncthreads();
    }

    for (int i = 0; i < 32; i++) {
        const int s = i & 1;
        float4 va[4];
        if (i < 31) {
            load_A_regs((i + 1) * 32, va);   // LDG in flight during compute
            load_B(s ^ 1, (i + 1) * 32);
        }
        compute(s);
        if (i < 31) {
            store_A(s ^ 1, va);
            asm volatile("cp.async.wait_group 0;" ::: "memory");
        }
        __syncthreads();
    }

    // ---- epilogue: acc -> g_q/g_k/g_v ----
    #pragma unroll
    for (int m = 0; m < 2; m++) {
        #pragma unroll
        for (int n = 0; n < 6; n++) {
            const int gc = wn * 96 + n * 16;
            const int mi = gc >> 6, lc = gc & 63;
            float* out = ((mi == 0) ? g_q : (mi == 1) ? g_k : g_v)
                       + (size_t)(row0 + wm * 32 + m * 16) * HH + lc;
            wmma::store_matrix_sync(out, acc[m][n], HH, wmma::mem_row_major);
        }
    }
}

// ---------------- attention pass 1 (unchanged from R1) --------------------
__global__ __launch_bounds__(128) void attn_partial(const int* __restrict__ pad_mask)
{
    const int bx = blockIdx.x;
    const int b = bx / NCHUNK;
    const int r = bx % NCHUNK;
    int qt = 0;
    while ((qt + 1) * (qt + 2) / 2 <= r) qt++;
    const int kc = r - qt * (qt + 1) / 2;

    const int tid = threadIdx.x;
    const int qrow = qt * 128 + tid;
    const int k0 = kc * 128;

    float q[HH];
    {
        const float* qp = g_q + ((size_t)(b * TT + qrow)) * HH;
        #pragma unroll
        for (int i = 0; i < 16; i++) {
            float4 t4 = *(const float4*)(qp + i * 4);
            q[i * 4 + 0] = t4.x * 0.03125f;
            q[i * 4 + 1] = t4.y * 0.03125f;
            q[i * 4 + 2] = t4.z * 0.03125f;
            q[i * 4 + 3] = t4.w * 0.03125f;
        }
    }

    float m = -1e30f, l = 0.f;
    float acc[HH];
    #pragma unroll
    for (int h = 0; h < HH; h++) acc[h] = 0.f;

    __shared__ float KS[64][64];
    __shared__ float VS[64][64];
    __shared__ int   PM[64];

    for (int t2 = 0; t2 < 2; t2++) {
        const int kbase = k0 + t2 * 64;
        #pragma unroll
        for (int i = tid; i < 1024; i += 128) {
            int row = i >> 4, c4 = (i & 15) << 2;
            size_t g = ((size_t)(b * TT + kbase + row)) * HH + c4;
            *(float4*)&KS[row][c4] = *(const float4*)&g_k[g];
            *(float4*)&VS[row][c4] = *(const float4*)&g_v[g];
        }
        if (tid < 64) PM[tid] = pad_mask[b * TT + kbase + tid];
        __syncthreads();

        for (int jc = 0; jc < 4; jc++) {
            float s[16];
            #pragma unroll
            for (int j = 0; j < 16; j++) {
                const int jj = jc * 16 + j;
                float d = 0.f;
                #pragma unroll
                for (int k4 = 0; k4 < 16; k4++) {
                    float4 kv = *(float4*)&KS[jj][k4 << 2];
                    d = fmaf(q[k4 * 4 + 0], kv.x, d);
                    d = fmaf(q[k4 * 4 + 1], kv.y, d);
                    d = fmaf(q[k4 * 4 + 2], kv.z, d);
                    d = fmaf(q[k4 * 4 + 3], kv.w, d);
                }
                const int jg = kbase + jj;
                s[j] = (jg <= qrow && PM[jj] != 0) ? d : -1e30f;
            }
            float mc = s[0];
            #pragma unroll
            for (int j = 1; j < 16; j++) mc = fmaxf(mc, s[j]);
            float mnew = fmaxf(m, mc);
            if (mnew <= -1e29f) continue;

            float alpha = __expf(m - mnew);
            m = mnew;
            l *= alpha;
            #pragma unroll
            for (int h = 0; h < HH; h++) acc[h] *= alpha;

            #pragma unroll
            for (int j = 0; j < 16; j++) {
                const int jj = jc * 16 + j;
                float p = __expf(s[j] - mnew);
                l += p;
                #pragma unroll
                for (int h4 = 0; h4 < 16; h4++) {
                    float4 vv = *(float4*)&VS[jj][h4 << 2];
                    acc[h4 * 4 + 0] = fmaf(p, vv.x, acc[h4 * 4 + 0]);
                    acc[h4 * 4 + 1] = fmaf(p, vv.y, acc[h4 * 4 + 1]);
                    acc[h4 * 4 + 2] = fmaf(p, vv.z, acc[h4 * 4 + 2]);
                    acc[h4 * 4 + 3] = fmaf(p, vv.w, acc[h4 * 4 + 3]);
                }
            }
        }
        __syncthreads();
    }

    const size_t ci = (size_t)bx;
    g_pm_[ci * 128 + tid] = m;
    g_pl_[ci * 128 + tid] = l;
    float* pa = g_pacc + ci * (HH * 128);
    #pragma unroll
    for (int h = 0; h < HH; h++) pa[h * 128 + tid] = acc[h];
}

// ---------------- attention pass 2 (unchanged) -----------------------------
__global__ __launch_bounds__(128) void attn_combine(float* __restrict__ out)
{
    const int qt = blockIdx.x;
    const int b = blockIdx.y;
    const int row = threadIdx.x;
    const int np = qt + 1;
    const size_t base = (size_t)b * NCHUNK + qt * (qt + 1) / 2;

    float mstar = -1e30f;
    for (int p = 0; p < np; p++)
        mstar = fmaxf(mstar, g_pm_[(base + p) * 128 + row]);

    float L = 0.f;
    float o[HH];
    #pragma unroll
    for (int h = 0; h < HH; h++) o[h] = 0.f;

    for (int p = 0; p < np; p++) {
        const size_t ci = base + p;
        float w = __expf(g_pm_[ci * 128 + row] - mstar);
        L += g_pl_[ci * 128 + row] * w;
        const float* pa = g_pacc + ci * (HH * 128);
        #pragma unroll
        for (int h = 0; h < HH; h++) o[h] = fmaf(w, pa[h * 128 + row], o[h]);
    }

    const float inv = 1.f / L;
    float* op = out + ((size_t)(b * TT + qt * 128 + row)) * HH;
    #pragma unroll
    for (int h4 = 0; h4 < 16; h4++) {
        float4 v = make_float4(o[h4 * 4 + 0] * inv, o[h4 * 4 + 1] * inv,
                               o[h4 * 4 + 2] * inv, o[h4 * 4 + 3] * inv);
        *(float4*)&op[h4 << 2] = v;
    }
}

// ---------------- launcher -------------------------------------------------
extern "C" void kernel_launch(void* const* d_in, const int* in_sizes, int n_in,
                              void* d_out, int out_size)
{
    const float* x        = (const float*)d_in[0];
    const int*   pad_mask = (const int*)d_in[1];
    const float* Wq       = (const float*)d_in[2];
    const float* Wk       = (const float*)d_in[3];
    const float* Wv       = (const float*)d_in[4];
    float* out = (float*)d_out;

    cudaFuncSetAttribute(proj_wmma, cudaFuncAttributeMaxDynamicSharedMemorySize, DYN_BYTES);

    wt_convert<<<768, 256>>>(Wq, Wk, Wv);
    proj_wmma<<<BT / 128, 256, DYN_BYTES>>>(x);
    attn_partial<<<BB * NCHUNK, 128>>>(pad_mask);
    attn_combine<<<dim3(16, BB), 128>>>(out);
}

// round 10
// speedup vs baseline: 1.5792x; 1.1878x over previous
#include <cuda_runtime.h>
#include <cuda_bf16.h>
#include <mma.h>
#include <cstdint>
#include <math.h>

using namespace nvcuda;

#define BB 8
#define TT 2048
#define CC 1024
#define HH 64
#define BT (BB*TT)

// ---------------- scratch (__device__ globals; no allocs allowed) ----------
// q/k/v pre-split bf16 hi/lo (q pre-scaled by 1/32), written by proj epilogue
__device__ __nv_bfloat16 g_qh[BT*HH];
__device__ __nv_bfloat16 g_ql[BT*HH];
__device__ __nv_bfloat16 g_kh[BT*HH];
__device__ __nv_bfloat16 g_kl[BT*HH];
__device__ __nv_bfloat16 g_vh[BT*HH];
__device__ __nv_bfloat16 g_vl[BT*HH];
// W split into bf16 hi/lo, [mi][k=0..1023][n=0..63]
__device__ __nv_bfloat16 g_wh[3*CC*HH];
__device__ __nv_bfloat16 g_wl[3*CC*HH];

// flash partials: g_pacc layout [chunk][row][h]  (row-major, coalesced combine)
#define NCHUNK 136
__device__ float g_pacc[(size_t)BB*NCHUNK*128*HH];
__device__ float g_pm_[(size_t)BB*NCHUNK*128];
__device__ float g_pl_[(size_t)BB*NCHUNK*128];

__device__ __forceinline__ void cp_async16(uint32_t dst, const void* src) {
    asm volatile("cp.async.cg.shared.global [%0], [%1], 16;"
                 :: "r"(dst), "l"(src) : "memory");
}
__device__ __forceinline__ uint32_t smem_u32(const void* p) {
    uint32_t a;
    asm("{ .reg .u64 t; cvta.to.shared.u64 t, %1; cvt.u32.u64 %0, t; }"
        : "=r"(a) : "l"(p));
    return a;
}

// ==================== W split pre-kernel ====================
__global__ __launch_bounds__(256) void wt_convert(
    const float* __restrict__ Wq, const float* __restrict__ Wk,
    const float* __restrict__ Wv)
{
    int idx = blockIdx.x * 256 + threadIdx.x;      // 3*1024*64 = 196608
    int mi = idx >> 16;
    int rem = idx & 65535;                         // k*64 + n
    const float* W = (mi == 0) ? Wq : (mi == 1) ? Wk : Wv;
    float w = W[rem];
    __nv_bfloat16 h = __float2bfloat16_rn(w);
    float r = w - __bfloat162float(h);
    g_wh[(size_t)mi * 65536 + rem] = h;
    g_wl[(size_t)mi * 65536 + rem] = __float2bfloat16_rn(r);
}

// ==================== wmma projection GEMM ====================
#define A_LDM 48
#define B_LDM 208
#define A_BYTES (128*A_LDM*2)
#define B_BYTES (32*B_LDM*2)
#define OFF_AL  A_BYTES
#define OFF_BH  (2*A_BYTES)
#define OFF_BL  (2*A_BYTES + B_BYTES)
#define STAGE_BYTES (2*A_BYTES + 2*B_BYTES)   // 51200
#define DYN_BYTES (2*STAGE_BYTES)             // 102400 (also fits 128x196 fp32 epi stage)
#define EPI_LDM 196

__global__ __launch_bounds__(256) void proj_wmma(const float* __restrict__ x)
{
    extern __shared__ char dyn[];
    char* sm = dyn;
    const uint32_t smb = smem_u32(dyn);
    const int tid = threadIdx.x;
    const int row0 = blockIdx.x * 128;

    const int warp = tid >> 5;
    const int wm = warp >> 1;
    const int wn = warp & 1;

    const int a_row = tid >> 1;
    const int a_c0 = (tid & 1) * 16;

    wmma::fragment<wmma::accumulator, 16, 16, 16, float> acc[2][6];
    #pragma unroll
    for (int m = 0; m < 2; m++)
        #pragma unroll
        for (int n = 0; n < 6; n++)
            wmma::fill_fragment(acc[m][n], 0.0f);

    auto load_B = [&](int stage, int kc) {
        const uint32_t bbase = smb + stage * STAGE_BYTES;
        #pragma unroll
        for (int t = 0; t < 6; t++) {
            int j = tid + t * 256;
            int prec = (j >= 768) ? 1 : 0;
            int r = j - prec * 768;
            int row = r / 24;
            int c = (r % 24) * 8;
            int mi = c >> 6, n = c & 63;
            const __nv_bfloat16* src = (prec ? g_wl : g_wh)
                + (size_t)mi * 65536 + (size_t)(kc + row) * HH + n;
            uint32_t dst = bbase + (prec ? OFF_BL : OFF_BH)
                         + (uint32_t)(row * B_LDM + c) * 2;
            cp_async16(dst, src);
        }
        asm volatile("cp.async.commit_group;" ::: "memory");
    };

    auto load_A_regs = [&](int kc, float4* va) {
        const float* px = x + (size_t)(row0 + a_row) * CC + kc + a_c0;
        #pragma unroll
        for (int i = 0; i < 4; i++) va[i] = *(const float4*)(px + i * 4);
    };

    auto store_A = [&](int stage, const float4* va) {
        float v[16];
        #pragma unroll
        for (int i = 0; i < 4; i++) {
            v[i*4+0] = va[i].x; v[i*4+1] = va[i].y;
            v[i*4+2] = va[i].z; v[i*4+3] = va[i].w;
        }
        __align__(16) __nv_bfloat16 h[16];
        __align__(16) __nv_bfloat16 l[16];
        #pragma unroll
        for (int e = 0; e < 16; e++) {
            h[e] = __float2bfloat16_rn(v[e]);
            l[e] = __float2bfloat16_rn(v[e] - __bfloat162float(h[e]));
        }
        char* ab = sm + stage * STAGE_BYTES + (size_t)(a_row * A_LDM + a_c0) * 2;
        *(uint4*)(ab)               = *(uint4*)(h);
        *(uint4*)(ab + 16)          = *(uint4*)(h + 8);
        *(uint4*)(ab + OFF_AL)      = *(uint4*)(l);
        *(uint4*)(ab + OFF_AL + 16) = *(uint4*)(l + 8);
    };

    auto compute = [&](int stage) {
        const __nv_bfloat16* Ah = (const __nv_bfloat16*)(sm + stage * STAGE_BYTES);
        const __nv_bfloat16* Al = (const __nv_bfloat16*)(sm + stage * STAGE_BYTES + OFF_AL);
        const __nv_bfloat16* Bh = (const __nv_bfloat16*)(sm + stage * STAGE_BYTES + OFF_BH);
        const __nv_bfloat16* Bl = (const __nv_bfloat16*)(sm + stage * STAGE_BYTES + OFF_BL);
        #pragma unroll
        for (int ks = 0; ks < 2; ks++) {
            wmma::fragment<wmma::matrix_a, 16, 16, 16, __nv_bfloat16, wmma::row_major> ah[2], al[2];
            #pragma unroll
            for (int m = 0; m < 2; m++) {
                const int r = wm * 32 + m * 16;
                wmma::load_matrix_sync(ah[m], Ah + r * A_LDM + ks * 16, A_LDM);
                wmma::load_matrix_sync(al[m], Al + r * A_LDM + ks * 16, A_LDM);
            }
            #pragma unroll
            for (int n = 0; n < 6; n++) {
                const int c = wn * 96 + n * 16;
                wmma::fragment<wmma::matrix_b, 16, 16, 16, __nv_bfloat16, wmma::row_major> bh, bl;
                wmma::load_matrix_sync(bh, Bh + ks * 16 * B_LDM + c, B_LDM);
                wmma::load_matrix_sync(bl, Bl + ks * 16 * B_LDM + c, B_LDM);
                #pragma unroll
                for (int m = 0; m < 2; m++) {
                    wmma::mma_sync(acc[m][n], ah[m], bh, acc[m][n]);
                    wmma::mma_sync(acc[m][n], ah[m], bl, acc[m][n]);
                    wmma::mma_sync(acc[m][n], al[m], bh, acc[m][n]);
                }
            }
        }
    };

    {
        float4 va[4];
        load_B(0, 0);
        load_A_regs(0, va);
        store_A(0, va);
        asm volatile("cp.async.wait_group 0;" ::: "memory");
        __syncthreads();
    }

    for (int i = 0; i < 32; i++) {
        const int s = i & 1;
        float4 va[4];
        if (i < 31) {
            load_A_regs((i + 1) * 32, va);
            load_B(s ^ 1, (i + 1) * 32);
        }
        compute(s);
        if (i < 31) {
            store_A(s ^ 1, va);
            asm volatile("cp.async.wait_group 0;" ::: "memory");
        }
        __syncthreads();
    }

    // ---- epilogue: stage fp32 in smem, then split-write bf16 hi/lo ----
    float* Sf = (float*)sm;                      // [128][EPI_LDM]
    #pragma unroll
    for (int m = 0; m < 2; m++)
        #pragma unroll
        for (int n = 0; n < 6; n++)
            wmma::store_matrix_sync(Sf + (wm * 32 + m * 16) * EPI_LDM + wn * 96 + n * 16,
                                    acc[m][n], EPI_LDM, wmma::mem_row_major);
    __syncthreads();

    {
        const int row = tid >> 1;
        const int half = tid & 1;
        const float* srow = Sf + row * EPI_LDM + half * 96;
        __nv_bfloat16* hi_arr[3] = {g_qh, g_kh, g_vh};
        __nv_bfloat16* lo_arr[3] = {g_ql, g_kl, g_vl};
        #pragma unroll
        for (int g = 0; g < 12; g++) {
            const int gc0 = half * 96 + g * 8;
            const int mi = gc0 >> 6, lc = gc0 & 63;
            const float scale = (mi == 0) ? 0.03125f : 1.0f;
            float4 v0 = *(const float4*)(srow + g * 8);
            float4 v1 = *(const float4*)(srow + g * 8 + 4);
            float vv[8] = {v0.x, v0.y, v0.z, v0.w, v1.x, v1.y, v1.z, v1.w};
            __align__(16) __nv_bfloat16 h[8];
            __align__(16) __nv_bfloat16 l[8];
            #pragma unroll
            for (int e = 0; e < 8; e++) {
                float f = vv[e] * scale;
                h[e] = __float2bfloat16_rn(f);
                l[e] = __float2bfloat16_rn(f - __bfloat162float(h[e]));
            }
            size_t dst = (size_t)(row0 + row) * HH + lc;
            *(uint4*)(hi_arr[mi] + dst) = *(uint4*)h;
            *(uint4*)(lo_arr[mi] + dst) = *(uint4*)l;
        }
    }
}

// ==================== wmma attention pass 1 ====================
// Block = one (128q x 128k) chunk. 256 threads (8 warps).
// smem: Qh Ql Kh Kl Vh Vl [128][64] bf16 (16KB each), S [128][132] fp32, PM.
// Ph reuses Kh/Kl region, Pl reuses Qh/Ql region after S is computed.
#define AQH 0
#define AQL 16384
#define AKH 32768
#define AKL 49152
#define AVH 65536
#define AVL 81920
#define AS  98304
#define S_LDM 132
#define APM (AS + 128*S_LDM*4)          // 165888
#define ATT_BYTES (APM + 512)           // 166400
#define APH AKH
#define APL AQH
#define P_LDM 128

__global__ __launch_bounds__(256) void attn_partial(const int* __restrict__ pad_mask)
{
    extern __shared__ char sm[];
    const uint32_t smb = smem_u32(sm);
    const int bx = blockIdx.x;
    const int b = bx / NCHUNK;
    const int r = bx % NCHUNK;
    int qt = 0;
    while ((qt + 1) * (qt + 2) / 2 <= r) qt++;
    const int kc = r - qt * (qt + 1) / 2;
    const int k0 = kc * 128;

    const int tid = threadIdx.x;
    const int warp = tid >> 5;
    const int wr = warp >> 1;           // 0..3
    const int wc = warp & 1;            // 0..1

    // ---- cooperative loads: 6 flat 16KB tiles ----
    {
        const size_t qoff = (size_t)(b * TT + qt * 128) * HH;
        const size_t koff = (size_t)(b * TT + k0) * HH;
        const __nv_bfloat16* srcs[6] = {g_qh + qoff, g_ql + qoff,
                                        g_kh + koff, g_kl + koff,
                                        g_vh + koff, g_vl + koff};
        #pragma unroll
        for (int i = 0; i < 24; i++) {
            int ch = tid + 256 * i;
            int tile = ch >> 10;
            int idx = ch & 1023;
            cp_async16(smb + tile * 16384 + idx * 16, srcs[tile] + idx * 8);
        }
        asm volatile("cp.async.commit_group;" ::: "memory");
        if (tid < 128) ((int*)(sm + APM))[tid] = pad_mask[b * TT + k0 + tid];
        asm volatile("cp.async.wait_group 0;" ::: "memory");
        __syncthreads();
    }

    const __nv_bfloat16* Qh = (const __nv_bfloat16*)(sm + AQH);
    const __nv_bfloat16* Ql = (const __nv_bfloat16*)(sm + AQL);
    const __nv_bfloat16* Kh = (const __nv_bfloat16*)(sm + AKH);
    const __nv_bfloat16* Kl = (const __nv_bfloat16*)(sm + AKL);
    const __nv_bfloat16* Vh = (const __nv_bfloat16*)(sm + AVH);
    const __nv_bfloat16* Vl = (const __nv_bfloat16*)(sm + AVL);
    float* Sf = (float*)(sm + AS);

    // ---- S = Q @ K^T (3-pass split), warp tile 32x64 ----
    {
        wmma::fragment<wmma::accumulator, 16, 16, 16, float> acc_s[2][4];
        #pragma unroll
        for (int m = 0; m < 2; m++)
            #pragma unroll
            for (int n = 0; n < 4; n++)
                wmma::fill_fragment(acc_s[m][n], 0.0f);

        const __nv_bfloat16* pa[3] = {Qh, Ql, Qh};
        const __nv_bfloat16* pb[3] = {Kh, Kh, Kl};
        #pragma unroll
        for (int p = 0; p < 3; p++) {
            #pragma unroll
            for (int k = 0; k < 4; k++) {
                wmma::fragment<wmma::matrix_a, 16, 16, 16, __nv_bfloat16, wmma::row_major> a[2];
                #pragma unroll
                for (int m = 0; m < 2; m++)
                    wmma::load_matrix_sync(a[m], pa[p] + (wr * 32 + m * 16) * HH + k * 16, HH);
                #pragma unroll
                for (int n = 0; n < 4; n++) {
                    wmma::fragment<wmma::matrix_b, 16, 16, 16, __nv_bfloat16, wmma::col_major> bfr;
                    wmma::load_matrix_sync(bfr, pb[p] + (wc * 64 + n * 16) * HH + k * 16, HH);
                    #pragma unroll
                    for (int m = 0; m < 2; m++)
                        wmma::mma_sync(acc_s[m][n], a[m], bfr, acc_s[m][n]);
                }
            }
        }
        #pragma unroll
        for (int m = 0; m < 2; m++)
            #pragma unroll
            for (int n = 0; n < 4; n++)
                wmma::store_matrix_sync(Sf + (wr * 32 + m * 16) * S_LDM + wc * 64 + n * 16,
                                        acc_s[m][n], S_LDM, wmma::mem_row_major);
    }
    __syncthreads();

    // ---- softmax (no online rescale: one chunk per block) ----
    __nv_bfloat16* Ph = (__nv_bfloat16*)(sm + APH);
    __nv_bfloat16* Pl = (__nv_bfloat16*)(sm + APL);
    if (tid < 128) {
        const float* Srow = Sf + tid * S_LDM;
        const int* PMs = (const int*)(sm + APM);
        const bool diag = (kc == qt);
        float mrow = -1e30f;
        #pragma unroll 8
        for (int c4 = 0; c4 < 32; c4++) {
            float4 s4 = ((const float4*)Srow)[c4];
            float sv[4] = {s4.x, s4.y, s4.z, s4.w};
            #pragma unroll
            for (int e = 0; e < 4; e++) {
                int c = c4 * 4 + e;
                if (PMs[c] != 0 && (!diag || c <= tid))
                    mrow = fmaxf(mrow, sv[e]);
            }
        }
        float l = 0.f;
        #pragma unroll 8
        for (int c4 = 0; c4 < 32; c4++) {
            float4 s4 = ((const float4*)Srow)[c4];
            float sv[4] = {s4.x, s4.y, s4.z, s4.w};
            __align__(8) __nv_bfloat16 ph[4];
            __align__(8) __nv_bfloat16 pl[4];
            #pragma unroll
            for (int e = 0; e < 4; e++) {
                int c = c4 * 4 + e;
                bool valid = (PMs[c] != 0) && (!diag || c <= tid);
                float p = valid ? __expf(sv[e] - mrow) : 0.f;
                l += p;
                ph[e] = __float2bfloat16_rn(p);
                pl[e] = __float2bfloat16_rn(p - __bfloat162float(ph[e]));
            }
            ((uint2*)(Ph + tid * P_LDM))[c4] = *(uint2*)ph;
            ((uint2*)(Pl + tid * P_LDM))[c4] = *(uint2*)pl;
        }
        g_pm_[(size_t)bx * 128 + tid] = mrow;
        g_pl_[(size_t)bx * 128 + tid] = l;
    }
    __syncthreads();

    // ---- O = P @ V (3-pass split), warp tile 32x32 ----
    {
        wmma::fragment<wmma::accumulator, 16, 16, 16, float> acc_o[2][2];
        #pragma unroll
        for (int m = 0; m < 2; m++)
            #pragma unroll
            for (int n = 0; n < 2; n++)
                wmma::fill_fragment(acc_o[m][n], 0.0f);

        const __nv_bfloat16* pa[3] = {Ph, Pl, Ph};
        const __nv_bfloat16* pb[3] = {Vh, Vh, Vl};
        #pragma unroll
        for (int p = 0; p < 3; p++) {
            #pragma unroll
            for (int k = 0; k < 8; k++) {
                wmma::fragment<wmma::matrix_a, 16, 16, 16, __nv_bfloat16, wmma::row_major> a[2];
                #pragma unroll
                for (int m = 0; m < 2; m++)
                    wmma::load_matrix_sync(a[m], pa[p] + (wr * 32 + m * 16) * P_LDM + k * 16, P_LDM);
                #pragma unroll
                for (int n = 0; n < 2; n++) {
                    wmma::fragment<wmma::matrix_b, 16, 16, 16, __nv_bfloat16, wmma::row_major> bfr;
                    wmma::load_matrix_sync(bfr, pb[p] + (k * 16) * HH + wc * 32 + n * 16, HH);
                    #pragma unroll
                    for (int m = 0; m < 2; m++)
                        wmma::mma_sync(acc_o[m][n], a[m], bfr, acc_o[m][n]);
                }
            }
        }
        float* pacc = g_pacc + (size_t)bx * (128 * HH);
        #pragma unroll
        for (int m = 0; m < 2; m++)
            #pragma unroll
            for (int n = 0; n < 2; n++)
                wmma::store_matrix_sync(pacc + (wr * 32 + m * 16) * HH + wc * 32 + n * 16,
                                        acc_o[m][n], HH, wmma::mem_row_major);
    }
}

// ==================== attention pass 2: combine (coalesced) ====================
// grid (16 qtiles, 8 batch, 2 row-halves) x 1024 threads.
// thread = (trow 0..63, cg 0..15): accumulates 4 h-cols over np chunks.
__global__ __launch_bounds__(1024) void attn_combine(float* __restrict__ out)
{
    const int qt = blockIdx.x;
    const int b = blockIdx.y;
    const int z = blockIdx.z;
    const int np = qt + 1;
    const size_t base = (size_t)b * NCHUNK + qt * (qt + 1) / 2;
    const int tid = threadIdx.x;

    __shared__ float WS[16][64];
    __shared__ float SI[64];

    if (tid < 64) {
        const int row = z * 64 + tid;
        float mstar = -1e30f;
        for (int p = 0; p < np; p++)
            mstar = fmaxf(mstar, g_pm_[(base + p) * 128 + row]);
        float L = 0.f;
        for (int p = 0; p < np; p++) {
            float w = __expf(g_pm_[(base + p) * 128 + row] - mstar);
            WS[p][tid] = w;
            L += g_pl_[(base + p) * 128 + row] * w;
        }
        SI[tid] = 1.f / L;
    }
    __syncthreads();

    const int trow = tid >> 4;
    const int cg = tid & 15;
    const int row = z * 64 + trow;

    float4 o = make_float4(0.f, 0.f, 0.f, 0.f);
    for (int p = 0; p < np; p++) {
        float w = WS[p][trow];
        const float* pa = g_pacc + (base + p) * (128 * HH) + row * HH + cg * 4;
        float4 v = *(const float4*)pa;
        o.x = fmaf(w, v.x, o.x);
        o.y = fmaf(w, v.y, o.y);
        o.z = fmaf(w, v.z, o.z);
        o.w = fmaf(w, v.w, o.w);
    }
    const float inv = SI[trow];
    float4 res = make_float4(o.x * inv, o.y * inv, o.z * inv, o.w * inv);
    *(float4*)&out[(size_t)(b * TT + qt * 128 + row) * HH + cg * 4] = res;
}

// ---------------- launcher -------------------------------------------------
extern "C" void kernel_launch(void* const* d_in, const int* in_sizes, int n_in,
                              void* d_out, int out_size)
{
    const float* x        = (const float*)d_in[0];
    const int*   pad_mask = (const int*)d_in[1];
    const float* Wq       = (const float*)d_in[2];
    const float* Wk       = (const float*)d_in[3];
    const float* Wv       = (const float*)d_in[4];
    float* out = (float*)d_out;

    cudaFuncSetAttribute(proj_wmma, cudaFuncAttributeMaxDynamicSharedMemorySize, DYN_BYTES);
    cudaFuncSetAttribute(attn_partial, cudaFuncAttributeMaxDynamicSharedMemorySize, ATT_BYTES);

    wt_convert<<<768, 256>>>(Wq, Wk, Wv);
    proj_wmma<<<BT / 128, 256, DYN_BYTES>>>(x);
    attn_partial<<<BB * NCHUNK, 256, ATT_BYTES>>>(pad_mask);
    attn_combine<<<dim3(16, BB, 2), 1024>>>(out);
}

// round 11
// speedup vs baseline: 1.9773x; 1.2520x over previous
#include <cuda_runtime.h>
#include <cuda_bf16.h>
#include <mma.h>
#include <cstdint>
#include <math.h>

using namespace nvcuda;

#define BB 8
#define TT 2048
#define CC 1024
#define HH 64
#define BT (BB*TT)

// ---------------- scratch (__device__ globals; no allocs allowed) ----------
// q/k/v pre-split bf16 hi/lo (q pre-scaled by 1/32), written by proj epilogue
__device__ __nv_bfloat16 g_qh[BT*HH];
__device__ __nv_bfloat16 g_ql[BT*HH];
__device__ __nv_bfloat16 g_kh[BT*HH];
__device__ __nv_bfloat16 g_kl[BT*HH];
__device__ __nv_bfloat16 g_vh[BT*HH];
__device__ __nv_bfloat16 g_vl[BT*HH];
// W split into bf16 hi/lo, [mi][k=0..1023][n=0..63]
__device__ __nv_bfloat16 g_wh[3*CC*HH];
__device__ __nv_bfloat16 g_wl[3*CC*HH];

// flash partials: g_pacc layout [chunk][row][h]
#define NCHUNK 136
__device__ float g_pacc[(size_t)BB*NCHUNK*128*HH];
__device__ float g_pm_[(size_t)BB*NCHUNK*128];
__device__ float g_pl_[(size_t)BB*NCHUNK*128];

__device__ __forceinline__ void cp_async16(uint32_t dst, const void* src) {
    asm volatile("cp.async.cg.shared.global [%0], [%1], 16;"
                 :: "r"(dst), "l"(src) : "memory");
}
__device__ __forceinline__ uint32_t smem_u32(const void* p) {
    uint32_t a;
    asm("{ .reg .u64 t; cvta.to.shared.u64 t, %1; cvt.u32.u64 %0, t; }"
        : "=r"(a) : "l"(p));
    return a;
}

// ==================== W split pre-kernel ====================
__global__ __launch_bounds__(256) void wt_convert(
    const float* __restrict__ Wq, const float* __restrict__ Wk,
    const float* __restrict__ Wv)
{
    int idx = blockIdx.x * 256 + threadIdx.x;
    int mi = idx >> 16;
    int rem = idx & 65535;
    const float* W = (mi == 0) ? Wq : (mi == 1) ? Wk : Wv;
    float w = W[rem];
    __nv_bfloat16 h = __float2bfloat16_rn(w);
    float r = w - __bfloat162float(h);
    g_wh[(size_t)mi * 65536 + rem] = h;
    g_wl[(size_t)mi * 65536 + rem] = __float2bfloat16_rn(r);
}

// ==================== wmma projection GEMM (unchanged from R10) ============
#define A_LDM 48
#define B_LDM 208
#define A_BYTES (128*A_LDM*2)
#define B_BYTES (32*B_LDM*2)
#define OFF_AL  A_BYTES
#define OFF_BH  (2*A_BYTES)
#define OFF_BL  (2*A_BYTES + B_BYTES)
#define STAGE_BYTES (2*A_BYTES + 2*B_BYTES)
#define DYN_BYTES (2*STAGE_BYTES)
#define EPI_LDM 196

__global__ __launch_bounds__(256) void proj_wmma(const float* __restrict__ x)
{
    extern __shared__ char dyn[];
    char* sm = dyn;
    const uint32_t smb = smem_u32(dyn);
    const int tid = threadIdx.x;
    const int row0 = blockIdx.x * 128;

    const int warp = tid >> 5;
    const int wm = warp >> 1;
    const int wn = warp & 1;

    const int a_row = tid >> 1;
    const int a_c0 = (tid & 1) * 16;

    wmma::fragment<wmma::accumulator, 16, 16, 16, float> acc[2][6];
    #pragma unroll
    for (int m = 0; m < 2; m++)
        #pragma unroll
        for (int n = 0; n < 6; n++)
            wmma::fill_fragment(acc[m][n], 0.0f);

    auto load_B = [&](int stage, int kc) {
        const uint32_t bbase = smb + stage * STAGE_BYTES;
        #pragma unroll
        for (int t = 0; t < 6; t++) {
            int j = tid + t * 256;
            int prec = (j >= 768) ? 1 : 0;
            int r = j - prec * 768;
            int row = r / 24;
            int c = (r % 24) * 8;
            int mi = c >> 6, n = c & 63;
            const __nv_bfloat16* src = (prec ? g_wl : g_wh)
                + (size_t)mi * 65536 + (size_t)(kc + row) * HH + n;
            uint32_t dst = bbase + (prec ? OFF_BL : OFF_BH)
                         + (uint32_t)(row * B_LDM + c) * 2;
            cp_async16(dst, src);
        }
        asm volatile("cp.async.commit_group;" ::: "memory");
    };

    auto load_A_regs = [&](int kc, float4* va) {
        const float* px = x + (size_t)(row0 + a_row) * CC + kc + a_c0;
        #pragma unroll
        for (int i = 0; i < 4; i++) va[i] = *(const float4*)(px + i * 4);
    };

    auto store_A = [&](int stage, const float4* va) {
        float v[16];
        #pragma unroll
        for (int i = 0; i < 4; i++) {
            v[i*4+0] = va[i].x; v[i*4+1] = va[i].y;
            v[i*4+2] = va[i].z; v[i*4+3] = va[i].w;
        }
        __align__(16) __nv_bfloat16 h[16];
        __align__(16) __nv_bfloat16 l[16];
        #pragma unroll
        for (int e = 0; e < 16; e++) {
            h[e] = __float2bfloat16_rn(v[e]);
            l[e] = __float2bfloat16_rn(v[e] - __bfloat162float(h[e]));
        }
        char* ab = sm + stage * STAGE_BYTES + (size_t)(a_row * A_LDM + a_c0) * 2;
        *(uint4*)(ab)               = *(uint4*)(h);
        *(uint4*)(ab + 16)          = *(uint4*)(h + 8);
        *(uint4*)(ab + OFF_AL)      = *(uint4*)(l);
        *(uint4*)(ab + OFF_AL + 16) = *(uint4*)(l + 8);
    };

    auto compute = [&](int stage) {
        const __nv_bfloat16* Ah = (const __nv_bfloat16*)(sm + stage * STAGE_BYTES);
        const __nv_bfloat16* Al = (const __nv_bfloat16*)(sm + stage * STAGE_BYTES + OFF_AL);
        const __nv_bfloat16* Bh = (const __nv_bfloat16*)(sm + stage * STAGE_BYTES + OFF_BH);
        const __nv_bfloat16* Bl = (const __nv_bfloat16*)(sm + stage * STAGE_BYTES + OFF_BL);
        #pragma unroll
        for (int ks = 0; ks < 2; ks++) {
            wmma::fragment<wmma::matrix_a, 16, 16, 16, __nv_bfloat16, wmma::row_major> ah[2], al[2];
            #pragma unroll
            for (int m = 0; m < 2; m++) {
                const int r = wm * 32 + m * 16;
                wmma::load_matrix_sync(ah[m], Ah + r * A_LDM + ks * 16, A_LDM);
                wmma::load_matrix_sync(al[m], Al + r * A_LDM + ks * 16, A_LDM);
            }
            #pragma unroll
            for (int n = 0; n < 6; n++) {
                const int c = wn * 96 + n * 16;
                wmma::fragment<wmma::matrix_b, 16, 16, 16, __nv_bfloat16, wmma::row_major> bh, bl;
                wmma::load_matrix_sync(bh, Bh + ks * 16 * B_LDM + c, B_LDM);
                wmma::load_matrix_sync(bl, Bl + ks * 16 * B_LDM + c, B_LDM);
                #pragma unroll
                for (int m = 0; m < 2; m++) {
                    wmma::mma_sync(acc[m][n], ah[m], bh, acc[m][n]);
                    wmma::mma_sync(acc[m][n], ah[m], bl, acc[m][n]);
                    wmma::mma_sync(acc[m][n], al[m], bh, acc[m][n]);
                }
            }
        }
    };

    {
        float4 va[4];
        load_B(0, 0);
        load_A_regs(0, va);
        store_A(0, va);
        asm volatile("cp.async.wait_group 0;" ::: "memory");
        __syncthreads();
    }

    for (int i = 0; i < 32; i++) {
        const int s = i & 1;
        float4 va[4];
        if (i < 31) {
            load_A_regs((i + 1) * 32, va);
            load_B(s ^ 1, (i + 1) * 32);
        }
        compute(s);
        if (i < 31) {
            store_A(s ^ 1, va);
            asm volatile("cp.async.wait_group 0;" ::: "memory");
        }
        __syncthreads();
    }

    float* Sf = (float*)sm;
    #pragma unroll
    for (int m = 0; m < 2; m++)
        #pragma unroll
        for (int n = 0; n < 6; n++)
            wmma::store_matrix_sync(Sf + (wm * 32 + m * 16) * EPI_LDM + wn * 96 + n * 16,
                                    acc[m][n], EPI_LDM, wmma::mem_row_major);
    __syncthreads();

    {
        const int row = tid >> 1;
        const int half = tid & 1;
        const float* srow = Sf + row * EPI_LDM + half * 96;
        __nv_bfloat16* hi_arr[3] = {g_qh, g_kh, g_vh};
        __nv_bfloat16* lo_arr[3] = {g_ql, g_kl, g_vl};
        #pragma unroll
        for (int g = 0; g < 12; g++) {
            const int gc0 = half * 96 + g * 8;
            const int mi = gc0 >> 6, lc = gc0 & 63;
            const float scale = (mi == 0) ? 0.03125f : 1.0f;
            float4 v0 = *(const float4*)(srow + g * 8);
            float4 v1 = *(const float4*)(srow + g * 8 + 4);
            float vv[8] = {v0.x, v0.y, v0.z, v0.w, v1.x, v1.y, v1.z, v1.w};
            __align__(16) __nv_bfloat16 h[8];
            __align__(16) __nv_bfloat16 l[8];
            #pragma unroll
            for (int e = 0; e < 8; e++) {
                float f = vv[e] * scale;
                h[e] = __float2bfloat16_rn(f);
                l[e] = __float2bfloat16_rn(f - __bfloat162float(h[e]));
            }
            size_t dst = (size_t)(row0 + row) * HH + lc;
            *(uint4*)(hi_arr[mi] + dst) = *(uint4*)h;
            *(uint4*)(lo_arr[mi] + dst) = *(uint4*)l;
        }
    }
}

// ==================== wmma attention pass 1 (padded smem) ====================
// Q/K/V tiles [128][QKV_LDM=80] bf16 (160B stride, 8-bank shift, 32B aligned).
// P tiles [128][P_LDM=144] bf16 (288B stride). S [128][132] fp32.
#define QKV_LDM 80
#define TILE_B (128*QKV_LDM*2)          // 20480
#define AQH 0
#define AQL (1*TILE_B)
#define AKH (2*TILE_B)
#define AKL (3*TILE_B)
#define AVH (4*TILE_B)
#define AVL (5*TILE_B)
#define AS  (6*TILE_B)                  // 122880
#define S_LDM 132
#define APM (AS + 128*S_LDM*4)          // 190464
#define ATT_BYTES (APM + 512)           // 190976
#define APH AKH
#define APL AQH
#define P_LDM 144

__global__ __launch_bounds__(256) void attn_partial(const int* __restrict__ pad_mask)
{
    extern __shared__ char sm[];
    const uint32_t smb = smem_u32(sm);
    const int bx = blockIdx.x;
    const int b = bx / NCHUNK;
    const int r = bx % NCHUNK;
    int qt = 0;
    while ((qt + 1) * (qt + 2) / 2 <= r) qt++;
    const int kc = r - qt * (qt + 1) / 2;
    const int k0 = kc * 128;

    const int tid = threadIdx.x;
    const int warp = tid >> 5;
    const int wr = warp >> 1;
    const int wc = warp & 1;

    // ---- cooperative loads into padded tiles ----
    {
        const size_t qoff = (size_t)(b * TT + qt * 128) * HH;
        const size_t koff = (size_t)(b * TT + k0) * HH;
        const __nv_bfloat16* srcs[6] = {g_qh + qoff, g_ql + qoff,
                                        g_kh + koff, g_kl + koff,
                                        g_vh + koff, g_vl + koff};
        #pragma unroll
        for (int i = 0; i < 24; i++) {
            int ch = tid + 256 * i;
            int tile = ch >> 10;
            int idx = ch & 1023;
            int row = idx >> 3, c8 = idx & 7;
            cp_async16(smb + tile * TILE_B + (uint32_t)(row * QKV_LDM + c8 * 8) * 2,
                       srcs[tile] + idx * 8);
        }
        asm volatile("cp.async.commit_group;" ::: "memory");
        if (tid < 128) ((int*)(sm + APM))[tid] = pad_mask[b * TT + k0 + tid];
        asm volatile("cp.async.wait_group 0;" ::: "memory");
        __syncthreads();
    }

    const __nv_bfloat16* Qh = (const __nv_bfloat16*)(sm + AQH);
    const __nv_bfloat16* Ql = (const __nv_bfloat16*)(sm + AQL);
    const __nv_bfloat16* Kh = (const __nv_bfloat16*)(sm + AKH);
    const __nv_bfloat16* Kl = (const __nv_bfloat16*)(sm + AKL);
    const __nv_bfloat16* Vh = (const __nv_bfloat16*)(sm + AVH);
    const __nv_bfloat16* Vl = (const __nv_bfloat16*)(sm + AVL);
    float* Sf = (float*)(sm + AS);

    // ---- S = Q @ K^T (3-pass split), warp tile 32x64 ----
    {
        wmma::fragment<wmma::accumulator, 16, 16, 16, float> acc_s[2][4];
        #pragma unroll
        for (int m = 0; m < 2; m++)
            #pragma unroll
            for (int n = 0; n < 4; n++)
                wmma::fill_fragment(acc_s[m][n], 0.0f);

        const __nv_bfloat16* pa[3] = {Qh, Ql, Qh};
        const __nv_bfloat16* pb[3] = {Kh, Kh, Kl};
        #pragma unroll
        for (int p = 0; p < 3; p++) {
            #pragma unroll
            for (int k = 0; k < 4; k++) {
                wmma::fragment<wmma::matrix_a, 16, 16, 16, __nv_bfloat16, wmma::row_major> a[2];
                #pragma unroll
                for (int m = 0; m < 2; m++)
                    wmma::load_matrix_sync(a[m], pa[p] + (wr * 32 + m * 16) * QKV_LDM + k * 16, QKV_LDM);
                #pragma unroll
                for (int n = 0; n < 4; n++) {
                    wmma::fragment<wmma::matrix_b, 16, 16, 16, __nv_bfloat16, wmma::col_major> bfr;
                    wmma::load_matrix_sync(bfr, pb[p] + (wc * 64 + n * 16) * QKV_LDM + k * 16, QKV_LDM);
                    #pragma unroll
                    for (int m = 0; m < 2; m++)
                        wmma::mma_sync(acc_s[m][n], a[m], bfr, acc_s[m][n]);
                }
            }
        }
        #pragma unroll
        for (int m = 0; m < 2; m++)
            #pragma unroll
            for (int n = 0; n < 4; n++)
                wmma::store_matrix_sync(Sf + (wr * 32 + m * 16) * S_LDM + wc * 64 + n * 16,
                                        acc_s[m][n], S_LDM, wmma::mem_row_major);
    }
    __syncthreads();

    // ---- softmax: 2 threads per row, pair-combined via shfl ----
    __nv_bfloat16* Ph = (__nv_bfloat16*)(sm + APH);
    __nv_bfloat16* Pl = (__nv_bfloat16*)(sm + APL);
    {
        const int row = tid >> 1;
        const int half = tid & 1;
        const float* Srow = Sf + row * S_LDM + half * 64;
        const int* PMs = (const int*)(sm + APM) + half * 64;
        const bool diag = (kc == qt);
        const int climit = row - half * 64;      // valid when local c <= climit (if diag)

        float mrow = -1e30f;
        float sv[64];
        #pragma unroll 4
        for (int c4 = 0; c4 < 16; c4++) {
            float4 s4 = ((const float4*)Srow)[c4];
            sv[c4*4+0] = s4.x; sv[c4*4+1] = s4.y;
            sv[c4*4+2] = s4.z; sv[c4*4+3] = s4.w;
        }
        #pragma unroll
        for (int c = 0; c < 64; c++)
            if (PMs[c] != 0 && (!diag || c <= climit))
                mrow = fmaxf(mrow, sv[c]);
        mrow = fmaxf(mrow, __shfl_xor_sync(0xFFFFFFFFu, mrow, 1));

        float l = 0.f;
        #pragma unroll 4
        for (int c4 = 0; c4 < 16; c4++) {
            __align__(8) __nv_bfloat16 ph[4];
            __align__(8) __nv_bfloat16 pl[4];
            #pragma unroll
            for (int e = 0; e < 4; e++) {
                int c = c4 * 4 + e;
                bool valid = (PMs[c] != 0) && (!diag || c <= climit);
                float p = valid ? __expf(sv[c] - mrow) : 0.f;
                l += p;
                ph[e] = __float2bfloat16_rn(p);
                pl[e] = __float2bfloat16_rn(p - __bfloat162float(ph[e]));
            }
            *(uint2*)(Ph + row * P_LDM + half * 64 + c4 * 4) = *(uint2*)ph;
            *(uint2*)(Pl + row * P_LDM + half * 64 + c4 * 4) = *(uint2*)pl;
        }
        l += __shfl_xor_sync(0xFFFFFFFFu, l, 1);
        if (half == 0) {
            g_pm_[(size_t)bx * 128 + row] = mrow;
            g_pl_[(size_t)bx * 128 + row] = l;
        }
    }
    __syncthreads();

    // ---- O = P @ V (3-pass split), warp tile 32x32 ----
    {
        wmma::fragment<wmma::accumulator, 16, 16, 16, float> acc_o[2][2];
        #pragma unroll
        for (int m = 0; m < 2; m++)
            #pragma unroll
            for (int n = 0; n < 2; n++)
                wmma::fill_fragment(acc_o[m][n], 0.0f);

        const __nv_bfloat16* pa[3] = {Ph, Pl, Ph};
        const __nv_bfloat16* pb[3] = {Vh, Vh, Vl};
        #pragma unroll
        for (int p = 0; p < 3; p++) {
            #pragma unroll
            for (int k = 0; k < 8; k++) {
                wmma::fragment<wmma::matrix_a, 16, 16, 16, __nv_bfloat16, wmma::row_major> a[2];
                #pragma unroll
                for (int m = 0; m < 2; m++)
                    wmma::load_matrix_sync(a[m], pa[p] + (wr * 32 + m * 16) * P_LDM + k * 16, P_LDM);
                #pragma unroll
                for (int n = 0; n < 2; n++) {
                    wmma::fragment<wmma::matrix_b, 16, 16, 16, __nv_bfloat16, wmma::row_major> bfr;
                    wmma::load_matrix_sync(bfr, pb[p] + (k * 16) * QKV_LDM + wc * 32 + n * 16, QKV_LDM);
                    #pragma unroll
                    for (int m = 0; m < 2; m++)
                        wmma::mma_sync(acc_o[m][n], a[m], bfr, acc_o[m][n]);
                }
            }
        }
        float* pacc = g_pacc + (size_t)bx * (128 * HH);
        #pragma unroll
        for (int m = 0; m < 2; m++)
            #pragma unroll
            for (int n = 0; n < 2; n++)
                wmma::store_matrix_sync(pacc + (wr * 32 + m * 16) * HH + wc * 32 + n * 16,
                                        acc_o[m][n], HH, wmma::mem_row_major);
    }
}

// ==================== attention pass 2: combine ====================
__global__ __launch_bounds__(1024) void attn_combine(float* __restrict__ out)
{
    const int qt = blockIdx.x;
    const int b = blockIdx.y;
    const int z = blockIdx.z;
    const int np = qt + 1;
    const size_t base = (size_t)b * NCHUNK + qt * (qt + 1) / 2;
    const int tid = threadIdx.x;

    __shared__ float WS[16][64];
    __shared__ float SI[64];

    if (tid < 64) {
        const int row = z * 64 + tid;
        float mstar = -1e30f;
        for (int p = 0; p < np; p++)
            mstar = fmaxf(mstar, g_pm_[(base + p) * 128 + row]);
        float L = 0.f;
        for (int p = 0; p < np; p++) {
            float w = __expf(g_pm_[(base + p) * 128 + row] - mstar);
            WS[p][tid] = w;
            L += g_pl_[(base + p) * 128 + row] * w;
        }
        SI[tid] = 1.f / L;
    }
    __syncthreads();

    const int trow = tid >> 4;
    const int cg = tid & 15;
    const int row = z * 64 + trow;

    float4 o = make_float4(0.f, 0.f, 0.f, 0.f);
    for (int p = 0; p < np; p++) {
        float w = WS[p][trow];
        const float* pa = g_pacc + (base + p) * (128 * HH) + row * HH + cg * 4;
        float4 v = *(const float4*)pa;
        o.x = fmaf(w, v.x, o.x);
        o.y = fmaf(w, v.y, o.y);
        o.z = fmaf(w, v.z, o.z);
        o.w = fmaf(w, v.w, o.w);
    }
    const float inv = SI[trow];
    float4 res = make_float4(o.x * inv, o.y * inv, o.z * inv, o.w * inv);
    *(float4*)&out[(size_t)(b * TT + qt * 128 + row) * HH + cg * 4] = res;
}

// ---------------- launcher -------------------------------------------------
extern "C" void kernel_launch(void* const* d_in, const int* in_sizes, int n_in,
                              void* d_out, int out_size)
{
    const float* x        = (const float*)d_in[0];
    const int*   pad_mask = (const int*)d_in[1];
    const float* Wq       = (const float*)d_in[2];
    const float* Wk       = (const float*)d_in[3];
    const float* Wv       = (const float*)d_in[4];
    float* out = (float*)d_out;

    cudaFuncSetAttribute(proj_wmma, cudaFuncAttributeMaxDynamicSharedMemorySize, DYN_BYTES);
    cudaFuncSetAttribute(attn_partial, cudaFuncAttributeMaxDynamicSharedMemorySize, ATT_BYTES);

    wt_convert<<<768, 256>>>(Wq, Wk, Wv);
    proj_wmma<<<BT / 128, 256, DYN_BYTES>>>(x);
    attn_partial<<<BB * NCHUNK, 256, ATT_BYTES>>>(pad_mask);
    attn_combine<<<dim3(16, BB, 2), 1024>>>(out);
}

// round 15
// speedup vs baseline: 2.0315x; 1.0274x over previous
#include <cuda_runtime.h>
#include <cuda_bf16.h>
#include <mma.h>
#include <cstdint>
#include <math.h>

using namespace nvcuda;

#define BB 8
#define TT 2048
#define CC 1024
#define HH 64
#define BT (BB*TT)

// ---------------- scratch (__device__ globals; no allocs allowed) ----------
__device__ __nv_bfloat16 g_qh[BT*HH];
__device__ __nv_bfloat16 g_ql[BT*HH];
__device__ __nv_bfloat16 g_kh[BT*HH];
__device__ __nv_bfloat16 g_kl[BT*HH];
__device__ __nv_bfloat16 g_vh[BT*HH];
__device__ __nv_bfloat16 g_vl[BT*HH];
// W split into bf16 hi/lo, [mi][k=0..1023][n=0..63]
__device__ __nv_bfloat16 g_wh[3*CC*HH];
__device__ __nv_bfloat16 g_wl[3*CC*HH];

// flash partials: 64-row q-tiles x 128-col k-chunks. 272 chunks per batch.
#define NCHUNK 272
__device__ float g_pacc[(size_t)BB*NCHUNK*64*HH];   // [chunk][row64][h]
__device__ float g_pm_[(size_t)BB*NCHUNK*64];
__device__ float g_pl_[(size_t)BB*NCHUNK*64];

__device__ __forceinline__ void cp_async16(uint32_t dst, const void* src) {
    asm volatile("cp.async.cg.shared.global [%0], [%1], 16;"
                 :: "r"(dst), "l"(src) : "memory");
}
__device__ __forceinline__ uint32_t smem_u32(const void* p) {
    uint32_t a;
    asm("{ .reg .u64 t; cvta.to.shared.u64 t, %1; cvt.u32.u64 %0, t; }"
        : "=r"(a) : "l"(p));
    return a;
}
// chunks before q-tile qt: base(2m)=m*m+m, base(2m+1)=(m+1)^2
__device__ __host__ __forceinline__ int chunkbase(int q) {
    int m = q >> 1;
    return (q & 1) ? (m + 1) * (m + 1) : m * m + m;
}

// ==================== W split pre-kernel ====================
__global__ __launch_bounds__(256) void wt_convert(
    const float* __restrict__ Wq, const float* __restrict__ Wk,
    const float* __restrict__ Wv)
{
    int idx = blockIdx.x * 256 + threadIdx.x;
    int mi = idx >> 16;
    int rem = idx & 65535;
    const float* W = (mi == 0) ? Wq : (mi == 1) ? Wk : Wv;
    float w = W[rem];
    __nv_bfloat16 h = __float2bfloat16_rn(w);
    float r = w - __bfloat162float(h);
    g_wh[(size_t)mi * 65536 + rem] = h;
    g_wl[(size_t)mi * 65536 + rem] = __float2bfloat16_rn(r);
}

// ==================== wmma projection GEMM (unchanged core) ================
#define A_LDM 48
#define B_LDM 208
#define A_BYTES (128*A_LDM*2)
#define B_BYTES (32*B_LDM*2)
#define OFF_AL  A_BYTES
#define OFF_BH  (2*A_BYTES)
#define OFF_BL  (2*A_BYTES + B_BYTES)
#define STAGE_BYTES (2*A_BYTES + 2*B_BYTES)
#define DYN_BYTES (2*STAGE_BYTES)
#define EPI_LDM 196

__global__ __launch_bounds__(256) void proj_wmma(const float* __restrict__ x)
{
    extern __shared__ char dyn[];
    char* sm = dyn;
    const uint32_t smb = smem_u32(dyn);
    const int tid = threadIdx.x;
    const int row0 = blockIdx.x * 128;

    const int warp = tid >> 5;
    const int wm = warp >> 1;
    const int wn = warp & 1;

    const int a_row = tid >> 1;
    const int a_c0 = (tid & 1) * 16;

    wmma::fragment<wmma::accumulator, 16, 16, 16, float> acc[2][6];
    #pragma unroll
    for (int m = 0; m < 2; m++)
        #pragma unroll
        for (int n = 0; n < 6; n++)
            wmma::fill_fragment(acc[m][n], 0.0f);

    auto load_B = [&](int stage, int kc) {
        const uint32_t bbase = smb + stage * STAGE_BYTES;
        #pragma unroll
        for (int t = 0; t < 6; t++) {
            int j = tid + t * 256;
            int prec = (j >= 768) ? 1 : 0;
            int r = j - prec * 768;
            int row = r / 24;
            int c = (r % 24) * 8;
            int mi = c >> 6, n = c & 63;
            const __nv_bfloat16* src = (prec ? g_wl : g_wh)
                + (size_t)mi * 65536 + (size_t)(kc + row) * HH + n;
            uint32_t dst = bbase + (prec ? OFF_BL : OFF_BH)
                         + (uint32_t)(row * B_LDM + c) * 2;
            cp_async16(dst, src);
        }
        asm volatile("cp.async.commit_group;" ::: "memory");
    };

    auto load_A_regs = [&](int kc, float4* va) {
        const float* px = x + (size_t)(row0 + a_row) * CC + kc + a_c0;
        #pragma unroll
        for (int i = 0; i < 4; i++) va[i] = *(const float4*)(px + i * 4);
    };

    auto store_A = [&](int stage, const float4* va) {
        float v[16];
        #pragma unroll
        for (int i = 0; i < 4; i++) {
            v[i*4+0] = va[i].x; v[i*4+1] = va[i].y;
            v[i*4+2] = va[i].z; v[i*4+3] = va[i].w;
        }
        __align__(16) __nv_bfloat16 h[16];
        __align__(16) __nv_bfloat16 l[16];
        #pragma unroll
        for (int e = 0; e < 16; e++) {
            h[e] = __float2bfloat16_rn(v[e]);
            l[e] = __float2bfloat16_rn(v[e] - __bfloat162float(h[e]));
        }
        char* ab = sm + stage * STAGE_BYTES + (size_t)(a_row * A_LDM + a_c0) * 2;
        *(uint4*)(ab)               = *(uint4*)(h);
        *(uint4*)(ab + 16)          = *(uint4*)(h + 8);
        *(uint4*)(ab + OFF_AL)      = *(uint4*)(l);
        *(uint4*)(ab + OFF_AL + 16) = *(uint4*)(l + 8);
    };

    auto compute = [&](int stage) {
        const __nv_bfloat16* Ah = (const __nv_bfloat16*)(sm + stage * STAGE_BYTES);
        const __nv_bfloat16* Al = (const __nv_bfloat16*)(sm + stage * STAGE_BYTES + OFF_AL);
        const __nv_bfloat16* Bh = (const __nv_bfloat16*)(sm + stage * STAGE_BYTES + OFF_BH);
        const __nv_bfloat16* Bl = (const __nv_bfloat16*)(sm + stage * STAGE_BYTES + OFF_BL);
        #pragma unroll
        for (int ks = 0; ks < 2; ks++) {
            wmma::fragment<wmma::matrix_a, 16, 16, 16, __nv_bfloat16, wmma::row_major> ah[2], al[2];
            #pragma unroll
            for (int m = 0; m < 2; m++) {
                const int r = wm * 32 + m * 16;
                wmma::load_matrix_sync(ah[m], Ah + r * A_LDM + ks * 16, A_LDM);
                wmma::load_matrix_sync(al[m], Al + r * A_LDM + ks * 16, A_LDM);
            }
            #pragma unroll
            for (int n = 0; n < 6; n++) {
                const int c = wn * 96 + n * 16;
                wmma::fragment<wmma::matrix_b, 16, 16, 16, __nv_bfloat16, wmma::row_major> bh, bl;
                wmma::load_matrix_sync(bh, Bh + ks * 16 * B_LDM + c, B_LDM);
                wmma::load_matrix_sync(bl, Bl + ks * 16 * B_LDM + c, B_LDM);
                #pragma unroll
                for (int m = 0; m < 2; m++) {
                    wmma::mma_sync(acc[m][n], ah[m], bh, acc[m][n]);
                    wmma::mma_sync(acc[m][n], ah[m], bl, acc[m][n]);
                    wmma::mma_sync(acc[m][n], al[m], bh, acc[m][n]);
                }
            }
        }
    };

    {
        float4 va[4];
        load_B(0, 0);
        load_A_regs(0, va);
        store_A(0, va);
        asm volatile("cp.async.wait_group 0;" ::: "memory");
        __syncthreads();
    }

    for (int i = 0; i < 32; i++) {
        const int s = i & 1;
        float4 va[4];
        if (i < 31) {
            load_A_regs((i + 1) * 32, va);
            load_B(s ^ 1, (i + 1) * 32);
        }
        compute(s);
        if (i < 31) {
            store_A(s ^ 1, va);
            asm volatile("cp.async.wait_group 0;" ::: "memory");
        }
        __syncthreads();
    }

    float* Sf = (float*)sm;
    #pragma unroll
    for (int m = 0; m < 2; m++)
        #pragma unroll
        for (int n = 0; n < 6; n++)
            wmma::store_matrix_sync(Sf + (wm * 32 + m * 16) * EPI_LDM + wn * 96 + n * 16,
                                    acc[m][n], EPI_LDM, wmma::mem_row_major);
    __syncthreads();

    {
        const int row = tid >> 1;
        const int half = tid & 1;
        const float* srow = Sf + row * EPI_LDM + half * 96;
        __nv_bfloat16* hi_arr[3] = {g_qh, g_kh, g_vh};
        __nv_bfloat16* lo_arr[3] = {g_ql, g_kl, g_vl};
        #pragma unroll
        for (int g = 0; g < 12; g++) {
            const int gc0 = half * 96 + g * 8;
            const int mi = gc0 >> 6, lc = gc0 & 63;
            const float scale = (mi == 0) ? 0.03125f : 1.0f;
            float4 v0 = *(const float4*)(srow + g * 8);
            float4 v1 = *(const float4*)(srow + g * 8 + 4);
            float vv[8] = {v0.x, v0.y, v0.z, v0.w, v1.x, v1.y, v1.z, v1.w};
            __align__(16) __nv_bfloat16 h[8];
            __align__(16) __nv_bfloat16 l[8];
            #pragma unroll
            for (int e = 0; e < 8; e++) {
                float f = vv[e] * scale;
                h[e] = __float2bfloat16_rn(f);
                l[e] = __float2bfloat16_rn(f - __bfloat162float(h[e]));
            }
            size_t dst = (size_t)(row0 + row) * HH + lc;
            *(uint4*)(hi_arr[mi] + dst) = *(uint4*)h;
            *(uint4*)(lo_arr[mi] + dst) = *(uint4*)l;
        }
    }
}

// ==================== wmma attention pass 1 (64q x 128k, 2 CTAs/SM) ========
// smem: Qh,Ql [64][72] | Kh,Kl [128][72] | Vh [128][72] | S [64][132] f32 | PM
// After S-phase: Vl [128][72] streams into the dead Qh/Ql region.
// P (64x136 bf16 x2) reuses the Kh/Kl region after softmax.
#define QLDM 72
#define AQH 0
#define AQL 9216
#define AKH 18432
#define AKL 36864
#define AVH 55296
#define AS  73728
#define S_LDM 132
#define APM 107520
#define ATT_BYTES 108032
#define AVL AQH                          // Vl overlays dead Q tiles (18432 B)
#define APH AKH
#define APL (AKH + 17408)
#define P_LDM 136

__global__ __launch_bounds__(256, 2) void attn_partial(const int* __restrict__ pad_mask)
{
    extern __shared__ char sm[];
    const uint32_t smb = smem_u32(sm);
    const int bx = blockIdx.x;
    const int b = bx / NCHUNK;
    const int r = bx % NCHUNK;
    int qt = 0;
    while (chunkbase(qt + 1) <= r) qt++;           // q-tile 0..31 (64 rows)
    const int kc = r - chunkbase(qt);              // k-chunk (128 cols)
    const int k0 = kc * 128;

    const int tid = threadIdx.x;
    const int warp = tid >> 5;
    const int wr = warp >> 1;                      // 0..3 -> rows wr*16
    const int wc = warp & 1;                       // 0..1

    const size_t koff = (size_t)(b * TT + k0) * HH;

    // ---- cooperative loads: Qh,Ql (1024 ch), Kh,Kl (2048 ch), Vh (1024 ch) ----
    {
        const size_t qoff = (size_t)(b * TT + qt * 64) * HH;
        #pragma unroll
        for (int i = 0; i < 16; i++) {
            int ch = tid + 256 * i;
            const __nv_bfloat16* src;
            uint32_t base;
            int idx;
            if (ch < 1024) {
                int t = ch >> 9; idx = ch & 511;
                src = (t ? g_ql : g_qh) + qoff + idx * 8;
                base = t ? AQL : AQH;
            } else if (ch < 3072) {
                int t = (ch - 1024) >> 10; idx = (ch - 1024) & 1023;
                src = (t ? g_kl : g_kh) + koff + idx * 8;
                base = t ? AKL : AKH;
            } else {
                idx = ch - 3072;
                src = g_vh + koff + idx * 8;
                base = AVH;
            }
            int row = idx >> 3, c8 = idx & 7;
            cp_async16(smb + base + (uint32_t)(row * QLDM + c8 * 8) * 2, src);
        }
        asm volatile("cp.async.commit_group;" ::: "memory");
        if (tid < 128) ((int*)(sm + APM))[tid] = pad_mask[b * TT + k0 + tid];
        asm volatile("cp.async.wait_group 0;" ::: "memory");
        __syncthreads();
    }

    const __nv_bfloat16* Qh = (const __nv_bfloat16*)(sm + AQH);
    const __nv_bfloat16* Ql = (const __nv_bfloat16*)(sm + AQL);
    const __nv_bfloat16* Kh = (const __nv_bfloat16*)(sm + AKH);
    const __nv_bfloat16* Kl = (const __nv_bfloat16*)(sm + AKL);
    const __nv_bfloat16* Vh = (const __nv_bfloat16*)(sm + AVH);
    float* Sf = (float*)(sm + AS);

    // ---- S = Q @ K^T (3-pass split), warp tile 16x64 ----
    {
        wmma::fragment<wmma::accumulator, 16, 16, 16, float> acc_s[4];
        #pragma unroll
        for (int n = 0; n < 4; n++) wmma::fill_fragment(acc_s[n], 0.0f);

        const __nv_bfloat16* pa[3] = {Qh, Ql, Qh};
        const __nv_bfloat16* pb[3] = {Kh, Kh, Kl};
        #pragma unroll
        for (int p = 0; p < 3; p++) {
            #pragma unroll
            for (int k = 0; k < 4; k++) {
                wmma::fragment<wmma::matrix_a, 16, 16, 16, __nv_bfloat16, wmma::row_major> a;
                wmma::load_matrix_sync(a, pa[p] + (wr * 16) * QLDM + k * 16, QLDM);
                #pragma unroll
                for (int n = 0; n < 4; n++) {
                    wmma::fragment<wmma::matrix_b, 16, 16, 16, __nv_bfloat16, wmma::col_major> bfr;
                    wmma::load_matrix_sync(bfr, pb[p] + (wc * 64 + n * 16) * QLDM + k * 16, QLDM);
                    wmma::mma_sync(acc_s[n], a, bfr, acc_s[n]);
                }
            }
        }
        #pragma unroll
        for (int n = 0; n < 4; n++)
            wmma::store_matrix_sync(Sf + (wr * 16) * S_LDM + wc * 64 + n * 16,
                                    acc_s[n], S_LDM, wmma::mem_row_major);
    }
    __syncthreads();   // Q tiles now dead; S ready

    // ---- stream Vl into dead Q region (overlaps softmax) ----
    {
        #pragma unroll
        for (int i = 0; i < 4; i++) {
            int idx = tid + 256 * i;               // 1024 chunks
            int row = idx >> 3, c8 = idx & 7;
            cp_async16(smb + AVL + (uint32_t)(row * QLDM + c8 * 8) * 2,
                       g_vl + koff + idx * 8);
        }
        asm volatile("cp.async.commit_group;" ::: "memory");
    }

    // ---- softmax: 4 threads per row (quad), rotated chunks, shfl reduce ----
    __nv_bfloat16* Ph = (__nv_bfloat16*)(sm + APH);
    __nv_bfloat16* Pl = (__nv_bfloat16*)(sm + APL);
    {
        const int row = tid >> 2;                  // 0..63
        const int q4 = tid & 3;
        const float* Srow = Sf + row * S_LDM;
        const int* PMs = (const int*)(sm + APM);
        int climit = 64 * qt + row - 128 * kc;     // >=127 means no causal mask
        if (climit > 127) climit = 127;

        float sv[32];
        float mrow = -1e30f;
        #pragma unroll
        for (int c4 = 0; c4 < 8; c4++) {
            const int cc = (c4 + 2 * q4) & 7;      // bank-rotated chunk
            float4 s4 = *(const float4*)(Srow + q4 * 32 + cc * 4);
            sv[cc*4+0] = s4.x; sv[cc*4+1] = s4.y;
            sv[cc*4+2] = s4.z; sv[cc*4+3] = s4.w;
        }
        #pragma unroll
        for (int c = 0; c < 32; c++) {
            const int gcol = q4 * 32 + c;
            if (PMs[gcol] != 0 && gcol <= climit)
                mrow = fmaxf(mrow, sv[c]);
        }
        mrow = fmaxf(mrow, __shfl_xor_sync(0xFFFFFFFFu, mrow, 1));
        mrow = fmaxf(mrow, __shfl_xor_sync(0xFFFFFFFFu, mrow, 2));

        float l = 0.f;
        #pragma unroll
        for (int c4 = 0; c4 < 8; c4++) {
            const int cc = (c4 + 2 * q4) & 7;
            __align__(8) __nv_bfloat16 ph[4];
            __align__(8) __nv_bfloat16 pl[4];
            #pragma unroll
            for (int e = 0; e < 4; e++) {
                const int gcol = q4 * 32 + cc * 4 + e;
                bool valid = (PMs[gcol] != 0) && (gcol <= climit);
                float p = valid ? __expf(sv[cc*4+e] - mrow) : 0.f;
                l += p;
                ph[e] = __float2bfloat16_rn(p);
                pl[e] = __float2bfloat16_rn(p - __bfloat162float(ph[e]));
            }
            *(uint2*)(Ph + row * P_LDM + q4 * 32 + cc * 4) = *(uint2*)ph;
            *(uint2*)(Pl + row * P_LDM + q4 * 32 + cc * 4) = *(uint2*)pl;
        }
        l += __shfl_xor_sync(0xFFFFFFFFu, l, 1);
        l += __shfl_xor_sync(0xFFFFFFFFu, l, 2);
        if (q4 == 0) {
            g_pm_[(size_t)bx * 64 + row] = mrow;
            g_pl_[(size_t)bx * 64 + row] = l;
        }
    }
    asm volatile("cp.async.wait_group 0;" ::: "memory");
    __syncthreads();   // P + Vl ready

    // ---- O = (Ph + Pl) @ Vh + Ph @ Vl (3-pass), warp tile 16x32 ----
    {
        const __nv_bfloat16* Vl = (const __nv_bfloat16*)(sm + AVL);
        wmma::fragment<wmma::accumulator, 16, 16, 16, float> acc_o[2];
        #pragma unroll
        for (int n = 0; n < 2; n++) wmma::fill_fragment(acc_o[n], 0.0f);

        const __nv_bfloat16* pa[3] = {Ph, Pl, Ph};
        const __nv_bfloat16* pb[3] = {Vh, Vh, Vl};
        #pragma unroll
        for (int p = 0; p < 3; p++) {
            #pragma unroll
            for (int k = 0; k < 8; k++) {
                wmma::fragment<wmma::matrix_a, 16, 16, 16, __nv_bfloat16, wmma::row_major> a;
                wmma::load_matrix_sync(a, pa[p] + (wr * 16) * P_LDM + k * 16, P_LDM);
                #pragma unroll
                for (int n = 0; n < 2; n++) {
                    wmma::fragment<wmma::matrix_b, 16, 16, 16, __nv_bfloat16, wmma::row_major> bfr;
                    wmma::load_matrix_sync(bfr, pb[p] + (k * 16) * QLDM + wc * 32 + n * 16, QLDM);
                    wmma::mma_sync(acc_o[n], a, bfr, acc_o[n]);
                }
            }
        }
        float* pacc = g_pacc + (size_t)bx * (64 * HH);
        #pragma unroll
        for (int n = 0; n < 2; n++)
            wmma::store_matrix_sync(pacc + (wr * 16) * HH + wc * 32 + n * 16,
                                    acc_o[n], HH, wmma::mem_row_major);
    }
}

// ==================== attention pass 2: combine ====================
// grid (32 qtiles, 8 batch) x 1024 threads; np = qt/2 + 1 (<=16)
__global__ __launch_bounds__(1024) void attn_combine(float* __restrict__ out)
{
    const int qt = blockIdx.x;
    const int b = blockIdx.y;
    const int np = (qt >> 1) + 1;
    const size_t base = (size_t)b * NCHUNK + chunkbase(qt);
    const int tid = threadIdx.x;

    __shared__ float WS[16][64];
    __shared__ float SI[64];

    if (tid < 64) {
        const int row = tid;
        float mstar = -1e30f;
        for (int p = 0; p < np; p++)
            mstar = fmaxf(mstar, g_pm_[(base + p) * 64 + row]);
        float L = 0.f;
        for (int p = 0; p < np; p++) {
            float w = __expf(g_pm_[(base + p) * 64 + row] - mstar);
            WS[p][row] = w;
            L += g_pl_[(base + p) * 64 + row] * w;
        }
        SI[row] = 1.f / L;
    }
    __syncthreads();

    const int trow = tid >> 4;
    const int cg = tid & 15;

    float4 o = make_float4(0.f, 0.f, 0.f, 0.f);
    for (int p = 0; p < np; p++) {
        float w = WS[p][trow];
        const float* pa = g_pacc + (base + p) * (64 * HH) + trow * HH + cg * 4;
        float4 v = *(const float4*)pa;
        o.x = fmaf(w, v.x, o.x);
        o.y = fmaf(w, v.y, o.y);
        o.z = fmaf(w, v.z, o.z);
        o.w = fmaf(w, v.w, o.w);
    }
    const float inv = SI[trow];
    float4 res = make_float4(o.x * inv, o.y * inv, o.z * inv, o.w * inv);
    *(float4*)&out[(size_t)(b * TT + qt * 64 + trow) * HH + cg * 4] = res;
}

// ---------------- launcher -------------------------------------------------
extern "C" void kernel_launch(void* const* d_in, const int* in_sizes, int n_in,
                              void* d_out, int out_size)
{
    const float* x        = (const float*)d_in[0];
    const int*   pad_mask = (const int*)d_in[1];
    const float* Wq       = (const float*)d_in[2];
    const float* Wk       = (const float*)d_in[3];
    const float* Wv       = (const float*)d_in[4];
    float* out = (float*)d_out;

    cudaFuncSetAttribute(proj_wmma, cudaFuncAttributeMaxDynamicSharedMemorySize, DYN_BYTES);
    cudaFuncSetAttribute(attn_partial, cudaFuncAttributeMaxDynamicSharedMemorySize, ATT_BYTES);

    wt_convert<<<768, 256>>>(Wq, Wk, Wv);
    proj_wmma<<<BT / 128, 256, DYN_BYTES>>>(x);
    attn_partial<<<BB * NCHUNK, 256, ATT_BYTES>>>(pad_mask);
    attn_combine<<<dim3(32, BB), 1024>>>(out);
}

// round 16
// speedup vs baseline: 2.4599x; 1.2109x over previous
#include <cuda_runtime.h>
#include <cuda_bf16.h>
#include <cuda_fp16.h>
#include <mma.h>
#include <cstdint>
#include <math.h>

using namespace nvcuda;

#define BB 8
#define TT 2048
#define CC 1024
#define HH 64
#define BT (BB*TT)

// ---------------- scratch (__device__ globals; no allocs allowed) ----------
// q/k/v in plain fp16 (q pre-scaled by 1/32), written by proj epilogue
__device__ __half g_qh[BT*HH];
__device__ __half g_kh[BT*HH];
__device__ __half g_vh[BT*HH];
// W split into bf16 hi/lo, [mi][k=0..1023][n=0..63] (projection stays exact)
__device__ __nv_bfloat16 g_wh[3*CC*HH];
__device__ __nv_bfloat16 g_wl[3*CC*HH];

// flash partials: 64-row q-tiles x 128-col k-chunks. 272 chunks per batch.
#define NCHUNK 272
__device__ float g_pacc[(size_t)BB*NCHUNK*64*HH];   // [chunk][row64][h]
__device__ float g_pm_[(size_t)BB*NCHUNK*64];
__device__ float g_pl_[(size_t)BB*NCHUNK*64];

__device__ __forceinline__ void cp_async16(uint32_t dst, const void* src) {
    asm volatile("cp.async.cg.shared.global [%0], [%1], 16;"
                 :: "r"(dst), "l"(src) : "memory");
}
__device__ __forceinline__ uint32_t smem_u32(const void* p) {
    uint32_t a;
    asm("{ .reg .u64 t; cvta.to.shared.u64 t, %1; cvt.u32.u64 %0, t; }"
        : "=r"(a) : "l"(p));
    return a;
}
// chunks before q-tile qt: base(2m)=m*m+m, base(2m+1)=(m+1)^2
__device__ __host__ __forceinline__ int chunkbase(int q) {
    int m = q >> 1;
    return (q & 1) ? (m + 1) * (m + 1) : m * m + m;
}

// ==================== W split pre-kernel ====================
__global__ __launch_bounds__(256) void wt_convert(
    const float* __restrict__ Wq, const float* __restrict__ Wk,
    const float* __restrict__ Wv)
{
    int idx = blockIdx.x * 256 + threadIdx.x;
    int mi = idx >> 16;
    int rem = idx & 65535;
    const float* W = (mi == 0) ? Wq : (mi == 1) ? Wk : Wv;
    float w = W[rem];
    __nv_bfloat16 h = __float2bfloat16_rn(w);
    float r = w - __bfloat162float(h);
    g_wh[(size_t)mi * 65536 + rem] = h;
    g_wl[(size_t)mi * 65536 + rem] = __float2bfloat16_rn(r);
}

// ==================== wmma projection GEMM (bf16-split, exact) =============
#define A_LDM 48
#define B_LDM 208
#define A_BYTES (128*A_LDM*2)
#define B_BYTES (32*B_LDM*2)
#define OFF_AL  A_BYTES
#define OFF_BH  (2*A_BYTES)
#define OFF_BL  (2*A_BYTES + B_BYTES)
#define STAGE_BYTES (2*A_BYTES + 2*B_BYTES)
#define DYN_BYTES (2*STAGE_BYTES)
#define EPI_LDM 196

__global__ __launch_bounds__(256) void proj_wmma(const float* __restrict__ x)
{
    extern __shared__ char dyn[];
    char* sm = dyn;
    const uint32_t smb = smem_u32(dyn);
    const int tid = threadIdx.x;
    const int row0 = blockIdx.x * 128;

    const int warp = tid >> 5;
    const int wm = warp >> 1;
    const int wn = warp & 1;

    const int a_row = tid >> 1;
    const int a_c0 = (tid & 1) * 16;

    wmma::fragment<wmma::accumulator, 16, 16, 16, float> acc[2][6];
    #pragma unroll
    for (int m = 0; m < 2; m++)
        #pragma unroll
        for (int n = 0; n < 6; n++)
            wmma::fill_fragment(acc[m][n], 0.0f);

    auto load_B = [&](int stage, int kc) {
        const uint32_t bbase = smb + stage * STAGE_BYTES;
        #pragma unroll
        for (int t = 0; t < 6; t++) {
            int j = tid + t * 256;
            int prec = (j >= 768) ? 1 : 0;
            int r = j - prec * 768;
            int row = r / 24;
            int c = (r % 24) * 8;
            int mi = c >> 6, n = c & 63;
            const __nv_bfloat16* src = (prec ? g_wl : g_wh)
                + (size_t)mi * 65536 + (size_t)(kc + row) * HH + n;
            uint32_t dst = bbase + (prec ? OFF_BL : OFF_BH)
                         + (uint32_t)(row * B_LDM + c) * 2;
            cp_async16(dst, src);
        }
        asm volatile("cp.async.commit_group;" ::: "memory");
    };

    auto load_A_regs = [&](int kc, float4* va) {
        const float* px = x + (size_t)(row0 + a_row) * CC + kc + a_c0;
        #pragma unroll
        for (int i = 0; i < 4; i++) va[i] = *(const float4*)(px + i * 4);
    };

    auto store_A = [&](int stage, const float4* va) {
        float v[16];
        #pragma unroll
        for (int i = 0; i < 4; i++) {
            v[i*4+0] = va[i].x; v[i*4+1] = va[i].y;
            v[i*4+2] = va[i].z; v[i*4+3] = va[i].w;
        }
        __align__(16) __nv_bfloat16 h[16];
        __align__(16) __nv_bfloat16 l[16];
        #pragma unroll
        for (int e = 0; e < 16; e++) {
            h[e] = __float2bfloat16_rn(v[e]);
            l[e] = __float2bfloat16_rn(v[e] - __bfloat162float(h[e]));
        }
        char* ab = sm + stage * STAGE_BYTES + (size_t)(a_row * A_LDM + a_c0) * 2;
        *(uint4*)(ab)               = *(uint4*)(h);
        *(uint4*)(ab + 16)          = *(uint4*)(h + 8);
        *(uint4*)(ab + OFF_AL)      = *(uint4*)(l);
        *(uint4*)(ab + OFF_AL + 16) = *(uint4*)(l + 8);
    };

    auto compute = [&](int stage) {
        const __nv_bfloat16* Ah = (const __nv_bfloat16*)(sm + stage * STAGE_BYTES);
        const __nv_bfloat16* Al = (const __nv_bfloat16*)(sm + stage * STAGE_BYTES + OFF_AL);
        const __nv_bfloat16* Bh = (const __nv_bfloat16*)(sm + stage * STAGE_BYTES + OFF_BH);
        const __nv_bfloat16* Bl = (const __nv_bfloat16*)(sm + stage * STAGE_BYTES + OFF_BL);
        #pragma unroll
        for (int ks = 0; ks < 2; ks++) {
            wmma::fragment<wmma::matrix_a, 16, 16, 16, __nv_bfloat16, wmma::row_major> ah[2], al[2];
            #pragma unroll
            for (int m = 0; m < 2; m++) {
                const int r = wm * 32 + m * 16;
                wmma::load_matrix_sync(ah[m], Ah + r * A_LDM + ks * 16, A_LDM);
                wmma::load_matrix_sync(al[m], Al + r * A_LDM + ks * 16, A_LDM);
            }
            #pragma unroll
            for (int n = 0; n < 6; n++) {
                const int c = wn * 96 + n * 16;
                wmma::fragment<wmma::matrix_b, 16, 16, 16, __nv_bfloat16, wmma::row_major> bh, bl;
                wmma::load_matrix_sync(bh, Bh + ks * 16 * B_LDM + c, B_LDM);
                wmma::load_matrix_sync(bl, Bl + ks * 16 * B_LDM + c, B_LDM);
                #pragma unroll
                for (int m = 0; m < 2; m++) {
                    wmma::mma_sync(acc[m][n], ah[m], bh, acc[m][n]);
                    wmma::mma_sync(acc[m][n], ah[m], bl, acc[m][n]);
                    wmma::mma_sync(acc[m][n], al[m], bh, acc[m][n]);
                }
            }
        }
    };

    {
        float4 va[4];
        load_B(0, 0);
        load_A_regs(0, va);
        store_A(0, va);
        asm volatile("cp.async.wait_group 0;" ::: "memory");
        __syncthreads();
    }

    for (int i = 0; i < 32; i++) {
        const int s = i & 1;
        float4 va[4];
        if (i < 31) {
            load_A_regs((i + 1) * 32, va);
            load_B(s ^ 1, (i + 1) * 32);
        }
        compute(s);
        if (i < 31) {
            store_A(s ^ 1, va);
            asm volatile("cp.async.wait_group 0;" ::: "memory");
        }
        __syncthreads();
    }

    float* Sf = (float*)sm;
    #pragma unroll
    for (int m = 0; m < 2; m++)
        #pragma unroll
        for (int n = 0; n < 6; n++)
            wmma::store_matrix_sync(Sf + (wm * 32 + m * 16) * EPI_LDM + wn * 96 + n * 16,
                                    acc[m][n], EPI_LDM, wmma::mem_row_major);
    __syncthreads();

    // epilogue: fp32 -> fp16, q scaled by 1/32
    {
        const int row = tid >> 1;
        const int half_ = tid & 1;
        const float* srow = Sf + row * EPI_LDM + half_ * 96;
        __half* out_arr[3] = {g_qh, g_kh, g_vh};
        #pragma unroll
        for (int g = 0; g < 12; g++) {
            const int gc0 = half_ * 96 + g * 8;
            const int mi = gc0 >> 6, lc = gc0 & 63;
            const float scale = (mi == 0) ? 0.03125f : 1.0f;
            float4 v0 = *(const float4*)(srow + g * 8);
            float4 v1 = *(const float4*)(srow + g * 8 + 4);
            float vv[8] = {v0.x, v0.y, v0.z, v0.w, v1.x, v1.y, v1.z, v1.w};
            __align__(16) __half h[8];
            #pragma unroll
            for (int e = 0; e < 8; e++)
                h[e] = __float2half_rn(vv[e] * scale);
            *(uint4*)(out_arr[mi] + (size_t)(row0 + row) * HH + lc) = *(uint4*)h;
        }
    }
}

// ==================== fp16 attention pass 1 (64q x 128k, 2 CTAs/SM) ========
// smem: Q [64][72] h | K [128][72] h | V [128][72] h | S [64][132] f | PM
// P (64x136 fp16) reuses the K region after softmax.
#define QLDM 72
#define AQ  0
#define AK  9216
#define AV  27648
#define AS  46080
#define S_LDM 132
#define APM 79872
#define ATT_BYTES 80384
#define AP  AK
#define P_LDM 136

__global__ __launch_bounds__(256, 2) void attn_partial(const int* __restrict__ pad_mask)
{
    extern __shared__ char sm[];
    const uint32_t smb = smem_u32(sm);
    const int bx = blockIdx.x;
    const int b = bx / NCHUNK;
    const int r = bx % NCHUNK;
    int qt = 0;
    while (chunkbase(qt + 1) <= r) qt++;           // q-tile 0..31 (64 rows)
    const int kc = r - chunkbase(qt);              // k-chunk (128 cols)
    const int k0 = kc * 128;

    const int tid = threadIdx.x;
    const int warp = tid >> 5;
    const int wr = warp >> 1;                      // 0..3 -> rows wr*16
    const int wc = warp & 1;                       // 0..1

    const size_t koff = (size_t)(b * TT + k0) * HH;

    // ---- cooperative loads: Q (512 ch), K (1024 ch), V (1024 ch) ----
    {
        const size_t qoff = (size_t)(b * TT + qt * 64) * HH;
        #pragma unroll
        for (int i = 0; i < 10; i++) {
            int ch = tid + 256 * i;                // 0..2559
            const __half* src;
            uint32_t base;
            int idx;
            if (ch < 512)       { idx = ch;        src = g_qh + qoff + idx * 8; base = AQ; }
            else if (ch < 1536) { idx = ch - 512;  src = g_kh + koff + idx * 8; base = AK; }
            else                { idx = ch - 1536; src = g_vh + koff + idx * 8; base = AV; }
            int row = idx >> 3, c8 = idx & 7;
            cp_async16(smb + base + (uint32_t)(row * QLDM + c8 * 8) * 2, src);
        }
        asm volatile("cp.async.commit_group;" ::: "memory");
        if (tid < 128) ((int*)(sm + APM))[tid] = pad_mask[b * TT + k0 + tid];
        asm volatile("cp.async.wait_group 0;" ::: "memory");
        __syncthreads();
    }

    const __half* Q = (const __half*)(sm + AQ);
    const __half* K = (const __half*)(sm + AK);
    const __half* V = (const __half*)(sm + AV);
    float* Sf = (float*)(sm + AS);

    // ---- S = Q @ K^T (single pass fp16), warp tile 16x64 ----
    {
        wmma::fragment<wmma::accumulator, 16, 16, 16, float> acc_s[4];
        #pragma unroll
        for (int n = 0; n < 4; n++) wmma::fill_fragment(acc_s[n], 0.0f);

        #pragma unroll
        for (int k = 0; k < 4; k++) {
            wmma::fragment<wmma::matrix_a, 16, 16, 16, __half, wmma::row_major> a;
            wmma::load_matrix_sync(a, Q + (wr * 16) * QLDM + k * 16, QLDM);
            #pragma unroll
            for (int n = 0; n < 4; n++) {
                wmma::fragment<wmma::matrix_b, 16, 16, 16, __half, wmma::col_major> bfr;
                wmma::load_matrix_sync(bfr, K + (wc * 64 + n * 16) * QLDM + k * 16, QLDM);
                wmma::mma_sync(acc_s[n], a, bfr, acc_s[n]);
            }
        }
        #pragma unroll
        for (int n = 0; n < 4; n++)
            wmma::store_matrix_sync(Sf + (wr * 16) * S_LDM + wc * 64 + n * 16,
                                    acc_s[n], S_LDM, wmma::mem_row_major);
    }
    __syncthreads();   // K dead; S ready

    // ---- softmax: 4 threads per row (quad), rotated chunks, shfl reduce ----
    __half* P = (__half*)(sm + AP);
    {
        const int row = tid >> 2;                  // 0..63
        const int q4 = tid & 3;
        const float* Srow = Sf + row * S_LDM;
        const int* PMs = (const int*)(sm + APM);
        int climit = 64 * qt + row - 128 * kc;     // >=127 means no causal mask
        if (climit > 127) climit = 127;

        float sv[32];
        float mrow = -1e30f;
        #pragma unroll
        for (int c4 = 0; c4 < 8; c4++) {
            const int cc = (c4 + 2 * q4) & 7;      // bank-rotated chunk
            float4 s4 = *(const float4*)(Srow + q4 * 32 + cc * 4);
            sv[cc*4+0] = s4.x; sv[cc*4+1] = s4.y;
            sv[cc*4+2] = s4.z; sv[cc*4+3] = s4.w;
        }
        #pragma unroll
        for (int c = 0; c < 32; c++) {
            const int gcol = q4 * 32 + c;
            if (PMs[gcol] != 0 && gcol <= climit)
                mrow = fmaxf(mrow, sv[c]);
        }
        mrow = fmaxf(mrow, __shfl_xor_sync(0xFFFFFFFFu, mrow, 1));
        mrow = fmaxf(mrow, __shfl_xor_sync(0xFFFFFFFFu, mrow, 2));

        float l = 0.f;
        #pragma unroll
        for (int c4 = 0; c4 < 8; c4++) {
            const int cc = (c4 + 2 * q4) & 7;
            __align__(8) __half ph[4];
            #pragma unroll
            for (int e = 0; e < 4; e++) {
                const int gcol = q4 * 32 + cc * 4 + e;
                bool valid = (PMs[gcol] != 0) && (gcol <= climit);
                float p = valid ? __expf(sv[cc*4+e] - mrow) : 0.f;
                l += p;
                ph[e] = __float2half_rn(p);
            }
            *(uint2*)(P + row * P_LDM + q4 * 32 + cc * 4) = *(uint2*)ph;
        }
        l += __shfl_xor_sync(0xFFFFFFFFu, l, 1);
        l += __shfl_xor_sync(0xFFFFFFFFu, l, 2);
        if (q4 == 0) {
            g_pm_[(size_t)bx * 64 + row] = mrow;
            g_pl_[(size_t)bx * 64 + row] = l;
        }
    }
    __syncthreads();   // P ready

    // ---- O = P @ V (single pass fp16), warp tile 16x32 ----
    {
        wmma::fragment<wmma::accumulator, 16, 16, 16, float> acc_o[2];
        #pragma unroll
        for (int n = 0; n < 2; n++) wmma::fill_fragment(acc_o[n], 0.0f);

        #pragma unroll
        for (int k = 0; k < 8; k++) {
            wmma::fragment<wmma::matrix_a, 16, 16, 16, __half, wmma::row_major> a;
            wmma::load_matrix_sync(a, P + (wr * 16) * P_LDM + k * 16, P_LDM);
            #pragma unroll
            for (int n = 0; n < 2; n++) {
                wmma::fragment<wmma::matrix_b, 16, 16, 16, __half, wmma::row_major> bfr;
                wmma::load_matrix_sync(bfr, V + (k * 16) * QLDM + wc * 32 + n * 16, QLDM);
                wmma::mma_sync(acc_o[n], a, bfr, acc_o[n]);
            }
        }
        float* pacc = g_pacc + (size_t)bx * (64 * HH);
        #pragma unroll
        for (int n = 0; n < 2; n++)
            wmma::store_matrix_sync(pacc + (wr * 16) * HH + wc * 32 + n * 16,
                                    acc_o[n], HH, wmma::mem_row_major);
    }
}

// ==================== attention pass 2: combine ====================
// grid (32 qtiles, 8 batch) x 1024 threads; np = qt/2 + 1 (<=16)
__global__ __launch_bounds__(1024) void attn_combine(float* __restrict__ out)
{
    const int qt = blockIdx.x;
    const int b = blockIdx.y;
    const int np = (qt >> 1) + 1;
    const size_t base = (size_t)b * NCHUNK + chunkbase(qt);
    const int tid = threadIdx.x;

    __shared__ float WS[16][64];
    __shared__ float SI[64];

    if (tid < 64) {
        const int row = tid;
        float mstar = -1e30f;
        for (int p = 0; p < np; p++)
            mstar = fmaxf(mstar, g_pm_[(base + p) * 64 + row]);
        float L = 0.f;
        for (int p = 0; p < np; p++) {
            float w = __expf(g_pm_[(base + p) * 64 + row] - mstar);
            WS[p][row] = w;
            L += g_pl_[(base + p) * 64 + row] * w;
        }
        SI[row] = 1.f / L;
    }
    __syncthreads();

    const int trow = tid >> 4;
    const int cg = tid & 15;

    float4 o = make_float4(0.f, 0.f, 0.f, 0.f);
    for (int p = 0; p < np; p++) {
        float w = WS[p][trow];
        const float* pa = g_pacc + (base + p) * (64 * HH) + trow * HH + cg * 4;
        float4 v = *(const float4*)pa;
        o.x = fmaf(w, v.x, o.x);
        o.y = fmaf(w, v.y, o.y);
        o.z = fmaf(w, v.z, o.z);
        o.w = fmaf(w, v.w, o.w);
    }
    const float inv = SI[trow];
    float4 res = make_float4(o.x * inv, o.y * inv, o.z * inv, o.w * inv);
    *(float4*)&out[(size_t)(b * TT + qt * 64 + trow) * HH + cg * 4] = res;
}

// ---------------- launcher -------------------------------------------------
extern "C" void kernel_launch(void* const* d_in, const int* in_sizes, int n_in,
                              void* d_out, int out_size)
{
    const float* x        = (const float*)d_in[0];
    const int*   pad_mask = (const int*)d_in[1];
    const float* Wq       = (const float*)d_in[2];
    const float* Wk       = (const float*)d_in[3];
    const float* Wv       = (const float*)d_in[4];
    float* out = (float*)d_out;

    cudaFuncSetAttribute(proj_wmma, cudaFuncAttributeMaxDynamicSharedMemorySize, DYN_BYTES);
    cudaFuncSetAttribute(attn_partial, cudaFuncAttributeMaxDynamicSharedMemorySize, ATT_BYTES);

    wt_convert<<<768, 256>>>(Wq, Wk, Wv);
    proj_wmma<<<BT / 128, 256, DYN_BYTES>>>(x);
    attn_partial<<<BB * NCHUNK, 256, ATT_BYTES>>>(pad_mask);
    attn_combine<<<dim3(32, BB), 1024>>>(out);
}

// round 17
// speedup vs baseline: 3.5329x; 1.4362x over previous
#include <cuda_runtime.h>
#include <cuda_bf16.h>
#include <cuda_fp16.h>
#include <mma.h>
#include <cstdint>
#include <math.h>

using namespace nvcuda;

#define BB 8
#define TT 2048
#define CC 1024
#define HH 64
#define BT (BB*TT)

// ---------------- scratch (__device__ globals; no allocs allowed) ----------
// q/k/v in plain fp16 (q pre-scaled by 1/32), written by proj epilogue
__device__ __half g_qh[BT*HH];
__device__ __half g_kh[BT*HH];
__device__ __half g_vh[BT*HH];
// W split into bf16 hi/lo, [mi][k=0..1023][n=0..63] (projection stays exact)
__device__ __nv_bfloat16 g_wh[3*CC*HH];
__device__ __nv_bfloat16 g_wl[3*CC*HH];

// flash partials: 64-row q-tiles x 128-col k-chunks. 272 chunks per batch.
#define NCHUNK 272
__device__ float g_pacc[(size_t)BB*NCHUNK*64*HH];   // [chunk][row64][h]
__device__ float g_pm_[(size_t)BB*NCHUNK*64];
__device__ float g_pl_[(size_t)BB*NCHUNK*64];

__device__ __forceinline__ void cp_async16(uint32_t dst, const void* src) {
    asm volatile("cp.async.cg.shared.global [%0], [%1], 16;"
                 :: "r"(dst), "l"(src) : "memory");
}
__device__ __forceinline__ uint32_t smem_u32(const void* p) {
    uint32_t a;
    asm("{ .reg .u64 t; cvta.to.shared.u64 t, %1; cvt.u32.u64 %0, t; }"
        : "=r"(a) : "l"(p));
    return a;
}
__device__ __forceinline__ void ldsm4(uint32_t* r, uint32_t a) {
    asm volatile("ldmatrix.sync.aligned.m8n8.x4.shared.b16 {%0,%1,%2,%3}, [%4];"
        : "=r"(r[0]), "=r"(r[1]), "=r"(r[2]), "=r"(r[3]) : "r"(a));
}
__device__ __forceinline__ void ldsm4t(uint32_t* r, uint32_t a) {
    asm volatile("ldmatrix.sync.aligned.m8n8.x4.trans.shared.b16 {%0,%1,%2,%3}, [%4];"
        : "=r"(r[0]), "=r"(r[1]), "=r"(r[2]), "=r"(r[3]) : "r"(a));
}
__device__ __forceinline__ void mma16816(float* d, const uint32_t* a, const uint32_t* b) {
    asm volatile("mma.sync.aligned.m16n8k16.row.col.f32.f16.f16.f32 "
        "{%0,%1,%2,%3}, {%4,%5,%6,%7}, {%8,%9}, {%0,%1,%2,%3};"
        : "+f"(d[0]), "+f"(d[1]), "+f"(d[2]), "+f"(d[3])
        : "r"(a[0]), "r"(a[1]), "r"(a[2]), "r"(a[3]), "r"(b[0]), "r"(b[1]));
}
__device__ __forceinline__ uint32_t pack_h2(float x, float y) {
    __half2 h = __floats2half2_rn(x, y);
    return *(uint32_t*)&h;
}
// chunks before q-tile qt: base(2m)=m*m+m, base(2m+1)=(m+1)^2
__device__ __host__ __forceinline__ int chunkbase(int q) {
    int m = q >> 1;
    return (q & 1) ? (m + 1) * (m + 1) : m * m + m;
}

// ==================== W split pre-kernel ====================
__global__ __launch_bounds__(256) void wt_convert(
    const float* __restrict__ Wq, const float* __restrict__ Wk,
    const float* __restrict__ Wv)
{
    int idx = blockIdx.x * 256 + threadIdx.x;
    int mi = idx >> 16;
    int rem = idx & 65535;
    const float* W = (mi == 0) ? Wq : (mi == 1) ? Wk : Wv;
    float w = W[rem];
    __nv_bfloat16 h = __float2bfloat16_rn(w);
    float r = w - __bfloat162float(h);
    g_wh[(size_t)mi * 65536 + rem] = h;
    g_wl[(size_t)mi * 65536 + rem] = __float2bfloat16_rn(r);
}

// ==================== wmma projection GEMM (bf16-split, exact) =============
#define A_LDM 48
#define B_LDM 208
#define A_BYTES (128*A_LDM*2)
#define B_BYTES (32*B_LDM*2)
#define OFF_AL  A_BYTES
#define OFF_BH  (2*A_BYTES)
#define OFF_BL  (2*A_BYTES + B_BYTES)
#define STAGE_BYTES (2*A_BYTES + 2*B_BYTES)
#define DYN_BYTES (2*STAGE_BYTES)
#define EPI_LDM 196

__global__ __launch_bounds__(256) void proj_wmma(const float* __restrict__ x)
{
    extern __shared__ char dyn[];
    char* sm = dyn;
    const uint32_t smb = smem_u32(dyn);
    const int tid = threadIdx.x;
    const int row0 = blockIdx.x * 128;

    const int warp = tid >> 5;
    const int wm = warp >> 1;
    const int wn = warp & 1;

    const int a_row = tid >> 1;
    const int a_c0 = (tid & 1) * 16;

    wmma::fragment<wmma::accumulator, 16, 16, 16, float> acc[2][6];
    #pragma unroll
    for (int m = 0; m < 2; m++)
        #pragma unroll
        for (int n = 0; n < 6; n++)
            wmma::fill_fragment(acc[m][n], 0.0f);

    auto load_B = [&](int stage, int kc) {
        const uint32_t bbase = smb + stage * STAGE_BYTES;
        #pragma unroll
        for (int t = 0; t < 6; t++) {
            int j = tid + t * 256;
            int prec = (j >= 768) ? 1 : 0;
            int r = j - prec * 768;
            int row = r / 24;
            int c = (r % 24) * 8;
            int mi = c >> 6, n = c & 63;
            const __nv_bfloat16* src = (prec ? g_wl : g_wh)
                + (size_t)mi * 65536 + (size_t)(kc + row) * HH + n;
            uint32_t dst = bbase + (prec ? OFF_BL : OFF_BH)
                         + (uint32_t)(row * B_LDM + c) * 2;
            cp_async16(dst, src);
        }
        asm volatile("cp.async.commit_group;" ::: "memory");
    };

    auto load_A_regs = [&](int kc, float4* va) {
        const float* px = x + (size_t)(row0 + a_row) * CC + kc + a_c0;
        #pragma unroll
        for (int i = 0; i < 4; i++) va[i] = *(const float4*)(px + i * 4);
    };

    auto store_A = [&](int stage, const float4* va) {
        float v[16];
        #pragma unroll
        for (int i = 0; i < 4; i++) {
            v[i*4+0] = va[i].x; v[i*4+1] = va[i].y;
            v[i*4+2] = va[i].z; v[i*4+3] = va[i].w;
        }
        __align__(16) __nv_bfloat16 h[16];
        __align__(16) __nv_bfloat16 l[16];
        #pragma unroll
        for (int e = 0; e < 16; e++) {
            h[e] = __float2bfloat16_rn(v[e]);
            l[e] = __float2bfloat16_rn(v[e] - __bfloat162float(h[e]));
        }
        char* ab = sm + stage * STAGE_BYTES + (size_t)(a_row * A_LDM + a_c0) * 2;
        *(uint4*)(ab)               = *(uint4*)(h);
        *(uint4*)(ab + 16)          = *(uint4*)(h + 8);
        *(uint4*)(ab + OFF_AL)      = *(uint4*)(l);
        *(uint4*)(ab + OFF_AL + 16) = *(uint4*)(l + 8);
    };

    auto compute = [&](int stage) {
        const __nv_bfloat16* Ah = (const __nv_bfloat16*)(sm + stage * STAGE_BYTES);
        const __nv_bfloat16* Al = (const __nv_bfloat16*)(sm + stage * STAGE_BYTES + OFF_AL);
        const __nv_bfloat16* Bh = (const __nv_bfloat16*)(sm + stage * STAGE_BYTES + OFF_BH);
        const __nv_bfloat16* Bl = (const __nv_bfloat16*)(sm + stage * STAGE_BYTES + OFF_BL);
        #pragma unroll
        for (int ks = 0; ks < 2; ks++) {
            wmma::fragment<wmma::matrix_a, 16, 16, 16, __nv_bfloat16, wmma::row_major> ah[2], al[2];
            #pragma unroll
            for (int m = 0; m < 2; m++) {
                const int r = wm * 32 + m * 16;
                wmma::load_matrix_sync(ah[m], Ah + r * A_LDM + ks * 16, A_LDM);
                wmma::load_matrix_sync(al[m], Al + r * A_LDM + ks * 16, A_LDM);
            }
            #pragma unroll
            for (int n = 0; n < 6; n++) {
                const int c = wn * 96 + n * 16;
                wmma::fragment<wmma::matrix_b, 16, 16, 16, __nv_bfloat16, wmma::row_major> bh, bl;
                wmma::load_matrix_sync(bh, Bh + ks * 16 * B_LDM + c, B_LDM);
                wmma::load_matrix_sync(bl, Bl + ks * 16 * B_LDM + c, B_LDM);
                #pragma unroll
                for (int m = 0; m < 2; m++) {
                    wmma::mma_sync(acc[m][n], ah[m], bh, acc[m][n]);
                    wmma::mma_sync(acc[m][n], ah[m], bl, acc[m][n]);
                    wmma::mma_sync(acc[m][n], al[m], bh, acc[m][n]);
                }
            }
        }
    };

    {
        float4 va[4];
        load_B(0, 0);
        load_A_regs(0, va);
        store_A(0, va);
        asm volatile("cp.async.wait_group 0;" ::: "memory");
        __syncthreads();
    }

    for (int i = 0; i < 32; i++) {
        const int s = i & 1;
        float4 va[4];
        if (i < 31) {
            load_A_regs((i + 1) * 32, va);
            load_B(s ^ 1, (i + 1) * 32);
        }
        compute(s);
        if (i < 31) {
            store_A(s ^ 1, va);
            asm volatile("cp.async.wait_group 0;" ::: "memory");
        }
        __syncthreads();
    }

    float* Sf = (float*)sm;
    #pragma unroll
    for (int m = 0; m < 2; m++)
        #pragma unroll
        for (int n = 0; n < 6; n++)
            wmma::store_matrix_sync(Sf + (wm * 32 + m * 16) * EPI_LDM + wn * 96 + n * 16,
                                    acc[m][n], EPI_LDM, wmma::mem_row_major);
    __syncthreads();

    // epilogue: fp32 -> fp16, q scaled by 1/32
    {
        const int row = tid >> 1;
        const int half_ = tid & 1;
        const float* srow = Sf + row * EPI_LDM + half_ * 96;
        __half* out_arr[3] = {g_qh, g_kh, g_vh};
        #pragma unroll
        for (int g = 0; g < 12; g++) {
            const int gc0 = half_ * 96 + g * 8;
            const int mi = gc0 >> 6, lc = gc0 & 63;
            const float scale = (mi == 0) ? 0.03125f : 1.0f;
            float4 v0 = *(const float4*)(srow + g * 8);
            float4 v1 = *(const float4*)(srow + g * 8 + 4);
            float vv[8] = {v0.x, v0.y, v0.z, v0.w, v1.x, v1.y, v1.z, v1.w};
            __align__(16) __half h[8];
            #pragma unroll
            for (int e = 0; e < 8; e++)
                h[e] = __float2half_rn(vv[e] * scale);
            *(uint4*)(out_arr[mi] + (size_t)(row0 + row) * HH + lc) = *(uint4*)h;
        }
    }
}

// ==================== FA2-style attention pass 1 ===========================
// 4 warps/block, 64q x 128k per block; warp = 16 rows x all 128 keys.
// S and P entirely in registers; smem only Q/K/V tiles + colmask.
// Layout (halfs, row stride QLDM=72 = 144B; ldmatrix bank shift 4/row):
#define QLDM 72
#define AQ  0
#define AK  9216
#define AV  27648
#define ACM 46080
#define ATT_BYTES 46208

__global__ __launch_bounds__(128, 3) void attn_partial(const int* __restrict__ pad_mask)
{
    extern __shared__ char sm[];
    const uint32_t smb = smem_u32(sm);
    const int bx = blockIdx.x;
    const int b = bx / NCHUNK;
    const int r = bx % NCHUNK;
    int qt = 0;
    while (chunkbase(qt + 1) <= r) qt++;           // q-tile 0..31 (64 rows)
    const int kc = r - chunkbase(qt);
    const int k0 = kc * 128;

    const int tid = threadIdx.x;
    const int lane = tid & 31;
    const int wr = tid >> 5;                       // warp 0..3 -> rows wr*16

    const size_t qoff = (size_t)(b * TT + qt * 64) * HH;
    const size_t koff = (size_t)(b * TT + k0) * HH;

    // ---- cooperative loads: Q(512) K(1024) V(1024) 16B chunks ----
    #pragma unroll
    for (int i = 0; i < 20; i++) {
        int ch = tid + 128 * i;
        const __half* src; uint32_t base; int idx;
        if (ch < 512)       { idx = ch;        src = g_qh + qoff + idx * 8; base = AQ; }
        else if (ch < 1536) { idx = ch - 512;  src = g_kh + koff + idx * 8; base = AK; }
        else                { idx = ch - 1536; src = g_vh + koff + idx * 8; base = AV; }
        int row = idx >> 3, c8 = idx & 7;
        cp_async16(smb + base + (uint32_t)(row * QLDM + c8 * 8) * 2, src);
    }
    asm volatile("cp.async.commit_group;" ::: "memory");

    // pad-mask -> 128-bit column mask via ballot (warp w owns cols w*32..)
    {
        int pm = pad_mask[b * TT + k0 + wr * 32 + lane];
        uint32_t bal = __ballot_sync(0xFFFFFFFFu, pm != 0);
        if (lane == 0) ((uint32_t*)(sm + ACM))[wr] = bal;
    }
    asm volatile("cp.async.wait_group 0;" ::: "memory");
    __syncthreads();

    // ---- A-fragments of Q (4 k-tiles) ----
    uint32_t qa[4][4];
    {
        uint32_t rowb = smb + AQ + (uint32_t)(wr * 16 + (lane & 15)) * 144
                      + (uint32_t)(lane >> 4) * 16;
        #pragma unroll
        for (int kt = 0; kt < 4; kt++) ldsm4(qa[kt], rowb + kt * 32);
    }

    // ---- S = Q @ K^T : 16 n8-fragments in registers ----
    float s[16][4];
    #pragma unroll
    for (int j = 0; j < 16; j++)
        #pragma unroll
        for (int e = 0; e < 4; e++) s[j][e] = 0.f;
    {
        uint32_t krow = smb + AK + (uint32_t)(((lane >> 4) << 3) + (lane & 7)) * 144
                      + (uint32_t)((lane >> 3) & 1) * 16;
        #pragma unroll
        for (int j2 = 0; j2 < 8; j2++) {
            #pragma unroll
            for (int kt = 0; kt < 4; kt++) {
                uint32_t kb[4];
                ldsm4(kb, krow + (uint32_t)(j2 * 16) * 144 + kt * 32);
                mma16816(s[2 * j2],     qa[kt], kb);
                mma16816(s[2 * j2 + 1], qa[kt], kb + 2);
            }
        }
    }

    // ---- softmax in registers (rows rowa = base+lane/4 and rowa+8) ----
    uint32_t cm[4];
    #pragma unroll
    for (int w = 0; w < 4; w++) cm[w] = ((uint32_t*)(sm + ACM))[w];
    const int rowa = qt * 64 + wr * 16 + (lane >> 2);

    float ma = -1e30f, mb = -1e30f;
    #pragma unroll
    for (int j = 0; j < 16; j++) {
        #pragma unroll
        for (int e = 0; e < 2; e++) {
            const int c = 8 * j + (lane & 3) * 2 + e;
            const bool ok = (cm[c >> 5] >> (c & 31)) & 1;
            const int gc = k0 + c;
            if (ok && gc <= rowa)     ma = fmaxf(ma, s[j][e]);
            if (ok && gc <= rowa + 8) mb = fmaxf(mb, s[j][e + 2]);
        }
    }
    ma = fmaxf(ma, __shfl_xor_sync(0xFFFFFFFFu, ma, 1));
    ma = fmaxf(ma, __shfl_xor_sync(0xFFFFFFFFu, ma, 2));
    mb = fmaxf(mb, __shfl_xor_sync(0xFFFFFFFFu, mb, 1));
    mb = fmaxf(mb, __shfl_xor_sync(0xFFFFFFFFu, mb, 2));

    float la = 0.f, lb = 0.f;
    #pragma unroll
    for (int j = 0; j < 16; j++) {
        #pragma unroll
        for (int e = 0; e < 2; e++) {
            const int c = 8 * j + (lane & 3) * 2 + e;
            const bool ok = (cm[c >> 5] >> (c & 31)) & 1;
            const int gc = k0 + c;
            float p0 = (ok && gc <= rowa)     ? __expf(s[j][e] - ma)     : 0.f;
            float p1 = (ok && gc <= rowa + 8) ? __expf(s[j][e + 2] - mb) : 0.f;
            s[j][e] = p0;     la += p0;
            s[j][e + 2] = p1; lb += p1;
        }
    }
    la += __shfl_xor_sync(0xFFFFFFFFu, la, 1);
    la += __shfl_xor_sync(0xFFFFFFFFu, la, 2);
    lb += __shfl_xor_sync(0xFFFFFFFFu, lb, 1);
    lb += __shfl_xor_sync(0xFFFFFFFFu, lb, 2);
    if ((lane & 3) == 0) {
        const int rloc = wr * 16 + (lane >> 2);
        g_pm_[(size_t)bx * 64 + rloc]     = ma;
        g_pm_[(size_t)bx * 64 + rloc + 8] = mb;
        g_pl_[(size_t)bx * 64 + rloc]     = la;
        g_pl_[(size_t)bx * 64 + rloc + 8] = lb;
    }

    // ---- pack P (C-frag -> A-frag identity), 8 k-tiles ----
    uint32_t pa[8][4];
    #pragma unroll
    for (int kt = 0; kt < 8; kt++) {
        pa[kt][0] = pack_h2(s[2*kt][0],     s[2*kt][1]);
        pa[kt][1] = pack_h2(s[2*kt][2],     s[2*kt][3]);
        pa[kt][2] = pack_h2(s[2*kt+1][0],   s[2*kt+1][1]);
        pa[kt][3] = pack_h2(s[2*kt+1][2],   s[2*kt+1][3]);
    }

    // ---- O = P @ V : 8 n8-fragments, V via ldmatrix.trans ----
    float o[8][4];
    #pragma unroll
    for (int j = 0; j < 8; j++)
        #pragma unroll
        for (int e = 0; e < 4; e++) o[j][e] = 0.f;
    {
        uint32_t vrow = smb + AV + (uint32_t)((((lane >> 3) & 1) << 3) + (lane & 7)) * 144
                      + (uint32_t)(lane >> 4) * 16;
        #pragma unroll
        for (int kt = 0; kt < 8; kt++) {
            #pragma unroll
            for (int n2 = 0; n2 < 4; n2++) {
                uint32_t vb[4];
                ldsm4t(vb, vrow + (uint32_t)(kt * 16) * 144 + n2 * 32);
                mma16816(o[2 * n2],     pa[kt], vb);
                mma16816(o[2 * n2 + 1], pa[kt], vb + 2);
            }
        }
    }

    // ---- store O partials [chunk][row][h] ----
    {
        float* pacc = g_pacc + (size_t)bx * (64 * HH);
        const int ra = wr * 16 + (lane >> 2);
        const int ca = (lane & 3) * 2;
        #pragma unroll
        for (int j = 0; j < 8; j++) {
            *(float2*)(pacc + ra * HH + 8 * j + ca)       = make_float2(o[j][0], o[j][1]);
            *(float2*)(pacc + (ra + 8) * HH + 8 * j + ca) = make_float2(o[j][2], o[j][3]);
        }
    }
}

// ==================== attention pass 2: combine ====================
// grid (32 qtiles, 8 batch) x 1024 threads; np = qt/2 + 1 (<=16)
__global__ __launch_bounds__(1024) void attn_combine(float* __restrict__ out)
{
    const int qt = blockIdx.x;
    const int b = blockIdx.y;
    const int np = (qt >> 1) + 1;
    const size_t base = (size_t)b * NCHUNK + chunkbase(qt);
    const int tid = threadIdx.x;

    __shared__ float WS[16][64];
    __shared__ float SI[64];

    if (tid < 64) {
        const int row = tid;
        float mstar = -1e30f;
        for (int p = 0; p < np; p++)
            mstar = fmaxf(mstar, g_pm_[(base + p) * 64 + row]);
        float L = 0.f;
        for (int p = 0; p < np; p++) {
            float w = __expf(g_pm_[(base + p) * 64 + row] - mstar);
            WS[p][row] = w;
            L += g_pl_[(base + p) * 64 + row] * w;
        }
        SI[row] = 1.f / L;
    }
    __syncthreads();

    const int trow = tid >> 4;
    const int cg = tid & 15;

    float4 o = make_float4(0.f, 0.f, 0.f, 0.f);
    for (int p = 0; p < np; p++) {
        float w = WS[p][trow];
        const float* pa = g_pacc + (base + p) * (64 * HH) + trow * HH + cg * 4;
        float4 v = *(const float4*)pa;
        o.x = fmaf(w, v.x, o.x);
        o.y = fmaf(w, v.y, o.y);
        o.z = fmaf(w, v.z, o.z);
        o.w = fmaf(w, v.w, o.w);
    }
    const float inv = SI[trow];
    float4 res = make_float4(o.x * inv, o.y * inv, o.z * inv, o.w * inv);
    *(float4*)&out[(size_t)(b * TT + qt * 64 + trow) * HH + cg * 4] = res;
}

// ---------------- launcher -------------------------------------------------
extern "C" void kernel_launch(void* const* d_in, const int* in_sizes, int n_in,
                              void* d_out, int out_size)
{
    const float* x        = (const float*)d_in[0];
    const int*   pad_mask = (const int*)d_in[1];
    const float* Wq       = (const float*)d_in[2];
    const float* Wk       = (const float*)d_in[3];
    const float* Wv       = (const float*)d_in[4];
    float* out = (float*)d_out;

    cudaFuncSetAttribute(proj_wmma, cudaFuncAttributeMaxDynamicSharedMemorySize, DYN_BYTES);
    cudaFuncSetAttribute(attn_partial, cudaFuncAttributeMaxDynamicSharedMemorySize, ATT_BYTES);

    wt_convert<<<768, 256>>>(Wq, Wk, Wv);
    proj_wmma<<<BT / 128, 256, DYN_BYTES>>>(x);
    attn_partial<<<BB * NCHUNK, 128, ATT_BYTES>>>(pad_mask);
    attn_combine<<<dim3(32, BB), 1024>>>(out);
}